// round 12
// baseline (speedup 1.0000x reference)
#include <cuda_runtime.h>
#include <cuda_bf16.h>
#include <cstdint>

#define NNODES 50000
#define NEDGES 800000
#define DIN    256
#define DH     128
#define NLAB   1000
#define NSCANB 196   // ceil(50000/256)

// ---------------- scratch (static device allocations; no cudaMalloc) --------
__device__ float g_ha[NNODES * DH];
__device__ float g_hb[NNODES * DH];
__device__ float g_agg[NNODES * DH];
__device__ float g_res[NNODES * DH];
__device__ int   g_cnt[NNODES];          // zero-init; left zero after each call
__device__ int   g_rowptr[NNODES + 1];
__device__ int   g_cursor[NNODES];
__device__ int   g_bsum[NSCANB];
__device__ uint4 g_edge[NEDGES];         // {src, self_w, ppi_w, pad} AoS

// ---------------- helpers ----------------------------------------------------
__device__ __forceinline__ uint32_t smem_u32(const void* p) {
    uint32_t a;
    asm("{ .reg .u64 t; cvta.to.shared.u64 t, %1; cvt.u32.u64 %0, t; }" : "=r"(a) : "l"(p));
    return a;
}
__device__ __forceinline__ uint32_t pack_bf2(float e0, float e1) {
    // low half = bf16(e0), high half = bf16(e1)
    uint32_t r;
    asm("cvt.rn.satfinite.bf16x2.f32 %0, %1, %2;" : "=r"(r) : "f"(e1), "f"(e0));
    return r;
}

#define LDSM4(r, addr)                                                          \
    asm volatile("ldmatrix.sync.aligned.m8n8.x4.shared.b16 {%0,%1,%2,%3}, [%4];"\
        : "=r"((r)[0]), "=r"((r)[1]), "=r"((r)[2]), "=r"((r)[3]) : "r"(addr))
#define LDSM4T(r, addr)                                                         \
    asm volatile("ldmatrix.sync.aligned.m8n8.x4.trans.shared.b16 {%0,%1,%2,%3}, [%4];"\
        : "=r"((r)[0]), "=r"((r)[1]), "=r"((r)[2]), "=r"((r)[3]) : "r"(addr))
#define MMA16816(d, a, b)                                                       \
    asm volatile("mma.sync.aligned.m16n8k16.row.col.f32.bf16.bf16.f32 "         \
        "{%0,%1,%2,%3}, {%4,%5,%6,%7}, {%8,%9}, {%0,%1,%2,%3};"                 \
        : "+f"((d)[0]), "+f"((d)[1]), "+f"((d)[2]), "+f"((d)[3])                \
        : "r"((a)[0]), "r"((a)[1]), "r"((a)[2]), "r"((a)[3]),                   \
          "r"((b)[0]), "r"((b)[1]))

// ---------------- CSR build -------------------------------------------------
__global__ void hist_kernel(const int* __restrict__ dst, int E) {
    int i = blockIdx.x * blockDim.x + threadIdx.x;
    if (i < E) atomicAdd(&g_cnt[dst[i]], 1);
}
__global__ void scanA_kernel() {
    __shared__ int wsum[8];
    int i = blockIdx.x * 256 + threadIdx.x;
    int lane = threadIdx.x & 31, wid = threadIdx.x >> 5;
    int v = (i < NNODES) ? g_cnt[i] : 0;
    #pragma unroll
    for (int off = 16; off > 0; off >>= 1) v += __shfl_down_sync(0xFFFFFFFFu, v, off);
    if (lane == 0) wsum[wid] = v;
    __syncthreads();
    if (threadIdx.x == 0) {
        int s = 0;
        #pragma unroll
        for (int w = 0; w < 8; w++) s += wsum[w];
        g_bsum[blockIdx.x] = s;
    }
}
__global__ void scanB_kernel() {
    __shared__ int wsc[8];
    int t = threadIdx.x;
    int lane = t & 31, wid = t >> 5;
    int v = (t < NSCANB) ? g_bsum[t] : 0;
    int incl = v;
    #pragma unroll
    for (int off = 1; off < 32; off <<= 1) {
        int u = __shfl_up_sync(0xFFFFFFFFu, incl, off);
        if (lane >= off) incl += u;
    }
    if (lane == 31) wsc[wid] = incl;
    __syncthreads();
    if (wid == 0) {
        int ws = (lane < 8) ? wsc[lane] : 0;
        #pragma unroll
        for (int off = 1; off < 8; off <<= 1) {
            int u = __shfl_up_sync(0xFFFFFFFFu, ws, off);
            if (lane >= off) ws += u;
        }
        if (lane < 8) wsc[lane] = ws;
    }
    __syncthreads();
    int excl = incl - v + (wid ? wsc[wid - 1] : 0);
    if (t < NSCANB) g_bsum[t] = excl;
    if (t == 255) g_rowptr[NNODES] = excl + v;
}
__global__ void scanC_kernel() {
    __shared__ int wsc[8];
    int i = blockIdx.x * 256 + threadIdx.x;
    int t = threadIdx.x, lane = t & 31, wid = t >> 5;
    int v = (i < NNODES) ? g_cnt[i] : 0;
    int incl = v;
    #pragma unroll
    for (int off = 1; off < 32; off <<= 1) {
        int u = __shfl_up_sync(0xFFFFFFFFu, incl, off);
        if (lane >= off) incl += u;
    }
    if (lane == 31) wsc[wid] = incl;
    __syncthreads();
    if (wid == 0) {
        int ws = (lane < 8) ? wsc[lane] : 0;
        #pragma unroll
        for (int off = 1; off < 8; off <<= 1) {
            int u = __shfl_up_sync(0xFFFFFFFFu, ws, off);
            if (lane >= off) ws += u;
        }
        if (lane < 8) wsc[lane] = ws;
    }
    __syncthreads();
    int excl = incl - v + (wid ? wsc[wid - 1] : 0) + g_bsum[blockIdx.x];
    if (i < NNODES) {
        g_rowptr[i] = excl;
        g_cursor[i] = excl;
        g_cnt[i] = 0;
    }
}
__global__ void scatter_kernel(const int* __restrict__ src, const int* __restrict__ dst,
                               const float* __restrict__ sw, const float* __restrict__ pw,
                               int E) {
    int i = blockIdx.x * blockDim.x + threadIdx.x;
    if (i < E) {
        int d = dst[i];
        int pos = atomicAdd(&g_cursor[d], 1);
        g_edge[pos] = make_uint4((uint32_t)src[i], __float_as_uint(sw[i]),
                                 __float_as_uint(pw[i]), 0u);
    }
}

// ---------------- aggregation: warp per dst node ----------------------------
__global__ void aggregate_kernel(const float* __restrict__ h) {
    int warp = (blockIdx.x * blockDim.x + threadIdx.x) >> 5;
    int lane = threadIdx.x & 31;
    if (warp >= NNODES) return;
    int beg = g_rowptr[warp];
    int end = g_rowptr[warp + 1];
    float4 as = make_float4(0.f, 0.f, 0.f, 0.f);
    float4 ap = make_float4(0.f, 0.f, 0.f, 0.f);
    int e = beg;
    for (; e + 1 < end; e += 2) {
        uint4 e0 = g_edge[e], e1 = g_edge[e + 1];
        int   s0 = (int)e0.x, s1 = (int)e1.x;
        float sw0 = __uint_as_float(e0.y), pw0 = __uint_as_float(e0.z);
        float sw1 = __uint_as_float(e1.y), pw1 = __uint_as_float(e1.z);
        float4 h0 = *reinterpret_cast<const float4*>(&h[(size_t)s0 * DH + lane * 4]);
        float4 h1 = *reinterpret_cast<const float4*>(&h[(size_t)s1 * DH + lane * 4]);
        as.x += sw0 * h0.x; as.y += sw0 * h0.y; as.z += sw0 * h0.z; as.w += sw0 * h0.w;
        ap.x += pw0 * h0.x; ap.y += pw0 * h0.y; ap.z += pw0 * h0.z; ap.w += pw0 * h0.w;
        as.x += sw1 * h1.x; as.y += sw1 * h1.y; as.z += sw1 * h1.z; as.w += sw1 * h1.w;
        ap.x += pw1 * h1.x; ap.y += pw1 * h1.y; ap.z += pw1 * h1.z; ap.w += pw1 * h1.w;
    }
    if (e < end) {
        uint4 e0 = g_edge[e];
        int   s0 = (int)e0.x;
        float sw0 = __uint_as_float(e0.y), pw0 = __uint_as_float(e0.z);
        float4 h0 = *reinterpret_cast<const float4*>(&h[(size_t)s0 * DH + lane * 4]);
        as.x += sw0 * h0.x; as.y += sw0 * h0.y; as.z += sw0 * h0.z; as.w += sw0 * h0.w;
        ap.x += pw0 * h0.x; ap.y += pw0 * h0.y; ap.z += pw0 * h0.z; ap.w += pw0 * h0.w;
    }
    *reinterpret_cast<float4*>(&g_res[(size_t)warp * DH + lane * 4]) = as;
    *reinterpret_cast<float4*>(&g_agg[(size_t)warp * DH + lane * 4]) = ap;
}

// ---------------- bf16-split GEMM on HMMA (128x128 block) -------------------
// Block 128x128, BK=32, 16 warps (32M x 32N), double buffer + reg prefetch.
#define SA_STRIDE 80
#define SB_STRIDE 272
#define OFF_A_HI 0
#define OFF_A_LO 10240
#define OFF_B_HI 20480
#define OFF_B_LO 29184
#define BUF_SZ   37888
#define OFF_BIAS 75776
#define SM_TOTAL 76288

template<bool RELU, bool ADDRES>
__global__ __launch_bounds__(512)
void mma_gemm(const float* __restrict__ A, const float* __restrict__ B,
              const float* __restrict__ bias, const float* __restrict__ Res,
              float* __restrict__ C, int M, int K, int Nc) {
    extern __shared__ __align__(16) char smem[];
    const uint32_t sb = smem_u32(smem);
    const int tid  = threadIdx.x;
    const int wid  = tid >> 5;
    const int lane = tid & 31;
    const int rowBase = blockIdx.x * 128;
    const int colBase = blockIdx.y * 128;
    const int wm = (wid >> 2) * 32;
    const int wn = (wid & 3) * 32;
    float* bias_s = reinterpret_cast<float*>(smem + OFF_BIAS);

    if (tid < 128) {
        int gc = colBase + tid;
        bias_s[tid] = (gc < Nc) ? bias[gc] : 0.f;
    }

    float4 pa[2], pb[2];

    auto loadA = [&](int k0) {
        #pragma unroll
        for (int u = 0; u < 2; u++) {
            int it = tid + u * 512;
            int r  = it >> 3;
            int kq = (it & 7) << 2;
            int gr = rowBase + r;
            pa[u] = (gr < M) ? *reinterpret_cast<const float4*>(&A[(size_t)gr * K + k0 + kq])
                             : make_float4(0.f, 0.f, 0.f, 0.f);
        }
    };
    auto loadB = [&](int k0) {
        #pragma unroll
        for (int u = 0; u < 2; u++) {
            int it = tid + u * 512;
            int kr = it >> 5;
            int nq = (it & 31) << 2;
            int gc = colBase + nq;
            const float* Brow = &B[(size_t)(k0 + kr) * Nc];
            float4 v;
            if (gc + 3 < Nc) {
                v = *reinterpret_cast<const float4*>(&Brow[gc]);
            } else {
                v.x = (gc     < Nc) ? Brow[gc]     : 0.f;
                v.y = (gc + 1 < Nc) ? Brow[gc + 1] : 0.f;
                v.z = (gc + 2 < Nc) ? Brow[gc + 2] : 0.f;
                v.w = (gc + 3 < Nc) ? Brow[gc + 3] : 0.f;
            }
            pb[u] = v;
        }
    };
    auto storeAB = [&](int buf) {
        const int base = buf * BUF_SZ;
        #pragma unroll
        for (int u = 0; u < 2; u++) {
            int it = tid + u * 512;
            int r  = it >> 3;
            int kq = (it & 7) << 2;
            float4 v = pa[u];
            uint32_t hp01 = pack_bf2(v.x, v.y);
            uint32_t hp23 = pack_bf2(v.z, v.w);
            float hx = __uint_as_float(hp01 << 16);
            float hy = __uint_as_float(hp01 & 0xFFFF0000u);
            float hz = __uint_as_float(hp23 << 16);
            float hw = __uint_as_float(hp23 & 0xFFFF0000u);
            uint32_t lp01 = pack_bf2(v.x - hx, v.y - hy);
            uint32_t lp23 = pack_bf2(v.z - hz, v.w - hw);
            int ad = base + r * SA_STRIDE + kq * 2;
            *reinterpret_cast<uint2*>(smem + OFF_A_HI + ad) = make_uint2(hp01, hp23);
            *reinterpret_cast<uint2*>(smem + OFF_A_LO + ad) = make_uint2(lp01, lp23);
        }
        #pragma unroll
        for (int u = 0; u < 2; u++) {
            int it = tid + u * 512;
            int kr = it >> 5;
            int nq = (it & 31) << 2;
            float4 v = pb[u];
            uint32_t hp01 = pack_bf2(v.x, v.y);
            uint32_t hp23 = pack_bf2(v.z, v.w);
            float hx = __uint_as_float(hp01 << 16);
            float hy = __uint_as_float(hp01 & 0xFFFF0000u);
            float hz = __uint_as_float(hp23 << 16);
            float hw = __uint_as_float(hp23 & 0xFFFF0000u);
            uint32_t lp01 = pack_bf2(v.x - hx, v.y - hy);
            uint32_t lp23 = pack_bf2(v.z - hz, v.w - hw);
            int ad = base + kr * SB_STRIDE + nq * 2;
            *reinterpret_cast<uint2*>(smem + OFF_B_HI + ad) = make_uint2(hp01, hp23);
            *reinterpret_cast<uint2*>(smem + OFF_B_LO + ad) = make_uint2(lp01, lp23);
        }
    };

    float acc[2][4][4];
    #pragma unroll
    for (int mt = 0; mt < 2; mt++)
        #pragma unroll
        for (int nt = 0; nt < 4; nt++)
            #pragma unroll
            for (int q = 0; q < 4; q++) acc[mt][nt][q] = 0.f;

    const int nch = K >> 5;
    loadA(0); loadB(0);
    storeAB(0);
    if (nch > 1) { loadA(32); loadB(32); }
    __syncthreads();

    for (int ch = 0; ch < nch; ch++) {
        const int base = (ch & 1) * BUF_SZ;
        #pragma unroll
        for (int kk = 0; kk < 32; kk += 16) {
            uint32_t ahi[2][4], alo[2][4];
            #pragma unroll
            for (int mt = 0; mt < 2; mt++) {
                int row = wm + mt * 16 + (lane & 15);
                int col = kk + ((lane >> 4) << 3);
                uint32_t aadr = sb + OFF_A_HI + base + row * SA_STRIDE + col * 2;
                LDSM4(ahi[mt], aadr);
                LDSM4(alo[mt], aadr + (OFF_A_LO - OFF_A_HI));
            }
            #pragma unroll
            for (int g = 0; g < 2; g++) {
                int krow = kk + ((lane >> 3) & 1) * 8 + (lane & 7);
                int ncol = wn + g * 16 + ((lane >> 4) << 3);
                uint32_t badr = sb + OFF_B_HI + base + krow * SB_STRIDE + ncol * 2;
                uint32_t bh[4], bl[4];
                LDSM4T(bh, badr);
                LDSM4T(bl, badr + (OFF_B_LO - OFF_B_HI));
                #pragma unroll
                for (int half = 0; half < 2; half++) {
                    int nt = g * 2 + half;
                    #pragma unroll
                    for (int mt = 0; mt < 2; mt++) {
                        MMA16816(acc[mt][nt], ahi[mt], bh + 2 * half);
                        MMA16816(acc[mt][nt], ahi[mt], bl + 2 * half);
                        MMA16816(acc[mt][nt], alo[mt], bh + 2 * half);
                    }
                }
            }
        }
        if (ch + 1 < nch) {
            storeAB((ch + 1) & 1);
            if (ch + 2 < nch) { loadA((ch + 2) << 5); loadB((ch + 2) << 5); }
            __syncthreads();
        }
    }

    const int g4 = lane >> 2;
    const int t4 = lane & 3;
    #pragma unroll
    for (int mt = 0; mt < 2; mt++) {
        #pragma unroll
        for (int half = 0; half < 2; half++) {
            int gr = rowBase + wm + mt * 16 + g4 + half * 8;
            if (gr >= M) continue;
            #pragma unroll
            for (int nt = 0; nt < 4; nt++) {
                int cl = wn + nt * 8 + t4 * 2;
                int gc = colBase + cl;
                float v0 = acc[mt][nt][half * 2]     + bias_s[cl];
                float v1 = acc[mt][nt][half * 2 + 1] + bias_s[cl + 1];
                if (RELU) { v0 = fmaxf(v0, 0.f); v1 = fmaxf(v1, 0.f); }
                if (gc + 1 < Nc) {
                    if (ADDRES) {
                        float2 rr = *reinterpret_cast<const float2*>(&Res[(size_t)gr * Nc + gc]);
                        v0 += rr.x; v1 += rr.y;
                    }
                    *reinterpret_cast<float2*>(&C[(size_t)gr * Nc + gc]) = make_float2(v0, v1);
                } else if (gc < Nc) {
                    if (ADDRES) v0 += Res[(size_t)gr * Nc + gc];
                    C[(size_t)gr * Nc + gc] = v0;
                }
            }
        }
    }
}

// ---------------- wide GEMM: 128x256 block for the output layer -------------
// 16 warps, warp tile 32M x 64N (R4 fragment layout), double buffer.
// Crossbar traffic per MAC is 25% lower than 128x128/32x32; half the blocks.
#define W_SA_STRIDE 80
#define W_SB_STRIDE 528
#define W_OFF_A_HI 0
#define W_OFF_A_LO 10240
#define W_OFF_B_HI 20480
#define W_OFF_B_LO 37376
#define W_BUF_SZ   54272
#define W_OFF_BIAS 108544
#define W_SM_TOTAL 109568

__global__ __launch_bounds__(512)
void mma_gemm_wide(const float* __restrict__ A, const float* __restrict__ B,
                   const float* __restrict__ bias, float* __restrict__ C,
                   int M, int K, int Nc) {
    extern __shared__ __align__(16) char smem[];
    const uint32_t sb = smem_u32(smem);
    const int tid  = threadIdx.x;
    const int wid  = tid >> 5;
    const int lane = tid & 31;
    const int rowBase = blockIdx.x * 128;
    const int colBase = blockIdx.y * 256;
    const int wm = (wid & 3) * 32;     // 4 warp rows
    const int wn = (wid >> 2) * 64;    // 4 warp cols x 64
    float* bias_s = reinterpret_cast<float*>(smem + W_OFF_BIAS);

    if (tid < 256) {
        int gc = colBase + tid;
        bias_s[tid] = (gc < Nc) ? bias[gc] : 0.f;
    }

    float4 pa[2], pb[4];

    auto loadA = [&](int k0) {
        #pragma unroll
        for (int u = 0; u < 2; u++) {
            int it = tid + u * 512;          // 1024: r=it>>3, kq=(it&7)*4
            int r  = it >> 3;
            int kq = (it & 7) << 2;
            int gr = rowBase + r;
            pa[u] = (gr < M) ? *reinterpret_cast<const float4*>(&A[(size_t)gr * K + k0 + kq])
                             : make_float4(0.f, 0.f, 0.f, 0.f);
        }
    };
    auto loadB = [&](int k0) {
        #pragma unroll
        for (int u = 0; u < 4; u++) {
            int it = tid + u * 512;          // 2048: kr=it>>6, nq=(it&63)*4
            int kr = it >> 6;
            int nq = (it & 63) << 2;
            int gc = colBase + nq;
            const float* Brow = &B[(size_t)(k0 + kr) * Nc];
            float4 v;
            if (gc + 3 < Nc) {
                v = *reinterpret_cast<const float4*>(&Brow[gc]);
            } else {
                v.x = (gc     < Nc) ? Brow[gc]     : 0.f;
                v.y = (gc + 1 < Nc) ? Brow[gc + 1] : 0.f;
                v.z = (gc + 2 < Nc) ? Brow[gc + 2] : 0.f;
                v.w = (gc + 3 < Nc) ? Brow[gc + 3] : 0.f;
            }
            pb[u] = v;
        }
    };
    auto storeAB = [&](int buf) {
        const int base = buf * W_BUF_SZ;
        #pragma unroll
        for (int u = 0; u < 2; u++) {
            int it = tid + u * 512;
            int r  = it >> 3;
            int kq = (it & 7) << 2;
            float4 v = pa[u];
            uint32_t hp01 = pack_bf2(v.x, v.y);
            uint32_t hp23 = pack_bf2(v.z, v.w);
            float hx = __uint_as_float(hp01 << 16);
            float hy = __uint_as_float(hp01 & 0xFFFF0000u);
            float hz = __uint_as_float(hp23 << 16);
            float hw = __uint_as_float(hp23 & 0xFFFF0000u);
            uint32_t lp01 = pack_bf2(v.x - hx, v.y - hy);
            uint32_t lp23 = pack_bf2(v.z - hz, v.w - hw);
            int ad = base + r * W_SA_STRIDE + kq * 2;
            *reinterpret_cast<uint2*>(smem + W_OFF_A_HI + ad) = make_uint2(hp01, hp23);
            *reinterpret_cast<uint2*>(smem + W_OFF_A_LO + ad) = make_uint2(lp01, lp23);
        }
        #pragma unroll
        for (int u = 0; u < 4; u++) {
            int it = tid + u * 512;
            int kr = it >> 6;
            int nq = (it & 63) << 2;
            float4 v = pb[u];
            uint32_t hp01 = pack_bf2(v.x, v.y);
            uint32_t hp23 = pack_bf2(v.z, v.w);
            float hx = __uint_as_float(hp01 << 16);
            float hy = __uint_as_float(hp01 & 0xFFFF0000u);
            float hz = __uint_as_float(hp23 << 16);
            float hw = __uint_as_float(hp23 & 0xFFFF0000u);
            uint32_t lp01 = pack_bf2(v.x - hx, v.y - hy);
            uint32_t lp23 = pack_bf2(v.z - hz, v.w - hw);
            int ad = base + kr * W_SB_STRIDE + nq * 2;
            *reinterpret_cast<uint2*>(smem + W_OFF_B_HI + ad) = make_uint2(hp01, hp23);
            *reinterpret_cast<uint2*>(smem + W_OFF_B_LO + ad) = make_uint2(lp01, lp23);
        }
    };

    float acc[2][8][4];
    #pragma unroll
    for (int mt = 0; mt < 2; mt++)
        #pragma unroll
        for (int nt = 0; nt < 8; nt++)
            #pragma unroll
            for (int q = 0; q < 4; q++) acc[mt][nt][q] = 0.f;

    const int nch = K >> 5;
    loadA(0); loadB(0);
    storeAB(0);
    if (nch > 1) { loadA(32); loadB(32); }
    __syncthreads();

    for (int ch = 0; ch < nch; ch++) {
        const int base = (ch & 1) * W_BUF_SZ;
        #pragma unroll
        for (int kk = 0; kk < 32; kk += 16) {
            uint32_t ahi[2][4], alo[2][4];
            #pragma unroll
            for (int mt = 0; mt < 2; mt++) {
                int row = wm + mt * 16 + (lane & 15);
                int col = kk + ((lane >> 4) << 3);
                uint32_t aadr = sb + W_OFF_A_HI + base + row * W_SA_STRIDE + col * 2;
                LDSM4(ahi[mt], aadr);
                LDSM4(alo[mt], aadr + (W_OFF_A_LO - W_OFF_A_HI));
            }
            #pragma unroll
            for (int g = 0; g < 4; g++) {
                int krow = kk + ((lane >> 3) & 1) * 8 + (lane & 7);
                int ncol = wn + g * 16 + ((lane >> 4) << 3);
                uint32_t badr = sb + W_OFF_B_HI + base + krow * W_SB_STRIDE + ncol * 2;
                uint32_t bh[4], bl[4];
                LDSM4T(bh, badr);
                LDSM4T(bl, badr + (W_OFF_B_LO - W_OFF_B_HI));
                #pragma unroll
                for (int half = 0; half < 2; half++) {
                    int nt = g * 2 + half;
                    #pragma unroll
                    for (int mt = 0; mt < 2; mt++) {
                        MMA16816(acc[mt][nt], ahi[mt], bh + 2 * half);
                        MMA16816(acc[mt][nt], ahi[mt], bl + 2 * half);
                        MMA16816(acc[mt][nt], alo[mt], bh + 2 * half);
                    }
                }
            }
        }
        if (ch + 1 < nch) {
            storeAB((ch + 1) & 1);
            if (ch + 2 < nch) { loadA((ch + 2) << 5); loadB((ch + 2) << 5); }
            __syncthreads();
        }
    }

    const int g4 = lane >> 2;
    const int t4 = lane & 3;
    #pragma unroll
    for (int mt = 0; mt < 2; mt++) {
        #pragma unroll
        for (int half = 0; half < 2; half++) {
            int gr = rowBase + wm + mt * 16 + g4 + half * 8;
            if (gr >= M) continue;
            #pragma unroll
            for (int nt = 0; nt < 8; nt++) {
                int cl = wn + nt * 8 + t4 * 2;
                int gc = colBase + cl;
                float v0 = acc[mt][nt][half * 2]     + bias_s[cl];
                float v1 = acc[mt][nt][half * 2 + 1] + bias_s[cl + 1];
                if (gc + 1 < Nc) {
                    *reinterpret_cast<float2*>(&C[(size_t)gr * Nc + gc]) = make_float2(v0, v1);
                } else if (gc < Nc) {
                    C[(size_t)gr * Nc + gc] = v0;
                }
            }
        }
    }
}

// ---------------- launch ----------------------------------------------------
extern "C" void kernel_launch(void* const* d_in, const int* in_sizes, int n_in,
                              void* d_out, int out_size) {
    const float* x      = (const float*)d_in[0];
    const int*   src    = (const int*)  d_in[1];
    const int*   dst    = (const int*)  d_in[2];
    const float* self_w = (const float*)d_in[3];
    const float* ppi_w  = (const float*)d_in[4];
    const float* W_in   = (const float*)d_in[5];
    const float* b_in   = (const float*)d_in[6];
    const float* W1     = (const float*)d_in[7];
    const float* b1     = (const float*)d_in[8];
    const float* W2     = (const float*)d_in[9];
    const float* b2     = (const float*)d_in[10];
    const float* W_out  = (const float*)d_in[11];
    const float* b_out  = (const float*)d_in[12];
    float* out = (float*)d_out;
    const int E = in_sizes[1];

    float *ha, *hb, *agg, *res;
    cudaGetSymbolAddress((void**)&ha,  g_ha);
    cudaGetSymbolAddress((void**)&hb,  g_hb);
    cudaGetSymbolAddress((void**)&agg, g_agg);
    cudaGetSymbolAddress((void**)&res, g_res);

    static cudaStream_t s2 = nullptr;
    static cudaEvent_t evFork = nullptr, evJoin = nullptr;
    if (s2 == nullptr) {
        cudaStreamCreateWithFlags(&s2, cudaStreamNonBlocking);
        cudaEventCreateWithFlags(&evFork, cudaEventDisableTiming);
        cudaEventCreateWithFlags(&evJoin, cudaEventDisableTiming);
    }

    cudaFuncSetAttribute(mma_gemm<true,  false>, cudaFuncAttributeMaxDynamicSharedMemorySize, SM_TOTAL);
    cudaFuncSetAttribute(mma_gemm<true,  true >, cudaFuncAttributeMaxDynamicSharedMemorySize, SM_TOTAL);
    cudaFuncSetAttribute(mma_gemm_wide, cudaFuncAttributeMaxDynamicSharedMemorySize, W_SM_TOTAL);

    const dim3 blk(512);
    const dim3 g_h((NNODES + 127) / 128, 1);
    const dim3 g_o((NNODES + 127) / 128, (NLAB + 255) / 256);
    const int agg_blocks = (NNODES * 32 + 255) / 256;

    // fork: CSR build chain on s2, input GEMM on main stream (independent)
    cudaEventRecord(evFork, 0);
    cudaStreamWaitEvent(s2, evFork, 0);

    hist_kernel<<<(E + 255) / 256, 256, 0, s2>>>(dst, E);
    scanA_kernel<<<NSCANB, 256, 0, s2>>>();
    scanB_kernel<<<1, 256, 0, s2>>>();
    scanC_kernel<<<NSCANB, 256, 0, s2>>>();
    scatter_kernel<<<(E + 255) / 256, 256, 0, s2>>>(src, dst, self_w, ppi_w, E);
    cudaEventRecord(evJoin, s2);

    // h = relu(x @ W_in + b_in)
    mma_gemm<true, false><<<g_h, blk, SM_TOTAL>>>(x, W_in, b_in, nullptr, ha, NNODES, DIN, DH);

    cudaStreamWaitEvent(0, evJoin, 0);

    // layer 1
    aggregate_kernel<<<agg_blocks, 256>>>(ha);
    mma_gemm<true, true><<<g_h, blk, SM_TOTAL>>>(agg, W1, b1, res, hb, NNODES, DH, DH);
    // layer 2
    aggregate_kernel<<<agg_blocks, 256>>>(hb);
    mma_gemm<true, true><<<g_h, blk, SM_TOTAL>>>(agg, W2, b2, res, ha, NNODES, DH, DH);
    // out = h @ W_out + b_out  (wide 128x256 kernel)
    mma_gemm_wide<<<g_o, blk, W_SM_TOTAL>>>(ha, W_out, b_out, out, NNODES, DH, NLAB);
}

// round 14
// speedup vs baseline: 1.0824x; 1.0824x over previous
#include <cuda_runtime.h>
#include <cuda_bf16.h>
#include <cuda_fp16.h>
#include <cstdint>

#define NNODES 50000
#define NEDGES 800000
#define DIN    256
#define DH     128
#define NLAB   1000
#define NSCANB 196   // ceil(50000/256)

// ---------------- scratch (static device allocations; no cudaMalloc) --------
__device__ float g_ha[NNODES * DH];
__device__ float g_hb[NNODES * DH];
__device__ float g_agg[NNODES * DH];
__device__ float g_res[NNODES * DH];
__device__ int   g_cnt[NNODES];          // zero-init; left zero after each call
__device__ int   g_rowptr[NNODES + 1];
__device__ int   g_cursor[NNODES];
__device__ int   g_bsum[NSCANB];
__device__ uint4 g_edge[NEDGES];         // {src, self_w, ppi_w, pad} AoS

// ---------------- helpers ----------------------------------------------------
__device__ __forceinline__ uint32_t smem_u32(const void* p) {
    uint32_t a;
    asm("{ .reg .u64 t; cvta.to.shared.u64 t, %1; cvt.u32.u64 %0, t; }" : "=r"(a) : "l"(p));
    return a;
}
__device__ __forceinline__ uint32_t pack_bf2(float e0, float e1) {
    // low half = bf16(e0), high half = bf16(e1)
    uint32_t r;
    asm("cvt.rn.satfinite.bf16x2.f32 %0, %1, %2;" : "=r"(r) : "f"(e1), "f"(e0));
    return r;
}
__device__ __forceinline__ uint32_t pack_h2(float e0, float e1) {
    __half2 h = __floats2half2_rn(e0, e1);   // e0 -> low
    return *reinterpret_cast<uint32_t*>(&h);
}
__device__ __forceinline__ float2 unpack_h2(uint32_t u) {
    __half2 h = *reinterpret_cast<__half2*>(&u);
    return __half22float2(h);
}

#define LDSM4(r, addr)                                                          \
    asm volatile("ldmatrix.sync.aligned.m8n8.x4.shared.b16 {%0,%1,%2,%3}, [%4];"\
        : "=r"((r)[0]), "=r"((r)[1]), "=r"((r)[2]), "=r"((r)[3]) : "r"(addr))
#define LDSM4T(r, addr)                                                         \
    asm volatile("ldmatrix.sync.aligned.m8n8.x4.trans.shared.b16 {%0,%1,%2,%3}, [%4];"\
        : "=r"((r)[0]), "=r"((r)[1]), "=r"((r)[2]), "=r"((r)[3]) : "r"(addr))
#define MMA16816(d, a, b)                                                       \
    asm volatile("mma.sync.aligned.m16n8k16.row.col.f32.bf16.bf16.f32 "         \
        "{%0,%1,%2,%3}, {%4,%5,%6,%7}, {%8,%9}, {%0,%1,%2,%3};"                 \
        : "+f"((d)[0]), "+f"((d)[1]), "+f"((d)[2]), "+f"((d)[3])                \
        : "r"((a)[0]), "r"((a)[1]), "r"((a)[2]), "r"((a)[3]),                   \
          "r"((b)[0]), "r"((b)[1]))
#define MMA16816H(d, a, b)                                                      \
    asm volatile("mma.sync.aligned.m16n8k16.row.col.f32.f16.f16.f32 "           \
        "{%0,%1,%2,%3}, {%4,%5,%6,%7}, {%8,%9}, {%0,%1,%2,%3};"                 \
        : "+f"((d)[0]), "+f"((d)[1]), "+f"((d)[2]), "+f"((d)[3])                \
        : "r"((a)[0]), "r"((a)[1]), "r"((a)[2]), "r"((a)[3]),                   \
          "r"((b)[0]), "r"((b)[1]))

// ---------------- CSR build -------------------------------------------------
__global__ void hist_kernel(const int* __restrict__ dst, int E) {
    int i = blockIdx.x * blockDim.x + threadIdx.x;
    if (i < E) atomicAdd(&g_cnt[dst[i]], 1);
}
__global__ void scanA_kernel() {
    __shared__ int wsum[8];
    int i = blockIdx.x * 256 + threadIdx.x;
    int lane = threadIdx.x & 31, wid = threadIdx.x >> 5;
    int v = (i < NNODES) ? g_cnt[i] : 0;
    #pragma unroll
    for (int off = 16; off > 0; off >>= 1) v += __shfl_down_sync(0xFFFFFFFFu, v, off);
    if (lane == 0) wsum[wid] = v;
    __syncthreads();
    if (threadIdx.x == 0) {
        int s = 0;
        #pragma unroll
        for (int w = 0; w < 8; w++) s += wsum[w];
        g_bsum[blockIdx.x] = s;
    }
}
__global__ void scanB_kernel() {
    __shared__ int wsc[8];
    int t = threadIdx.x;
    int lane = t & 31, wid = t >> 5;
    int v = (t < NSCANB) ? g_bsum[t] : 0;
    int incl = v;
    #pragma unroll
    for (int off = 1; off < 32; off <<= 1) {
        int u = __shfl_up_sync(0xFFFFFFFFu, incl, off);
        if (lane >= off) incl += u;
    }
    if (lane == 31) wsc[wid] = incl;
    __syncthreads();
    if (wid == 0) {
        int ws = (lane < 8) ? wsc[lane] : 0;
        #pragma unroll
        for (int off = 1; off < 8; off <<= 1) {
            int u = __shfl_up_sync(0xFFFFFFFFu, ws, off);
            if (lane >= off) ws += u;
        }
        if (lane < 8) wsc[lane] = ws;
    }
    __syncthreads();
    int excl = incl - v + (wid ? wsc[wid - 1] : 0);
    if (t < NSCANB) g_bsum[t] = excl;
    if (t == 255) g_rowptr[NNODES] = excl + v;
}
__global__ void scanC_kernel() {
    __shared__ int wsc[8];
    int i = blockIdx.x * 256 + threadIdx.x;
    int t = threadIdx.x, lane = t & 31, wid = t >> 5;
    int v = (i < NNODES) ? g_cnt[i] : 0;
    int incl = v;
    #pragma unroll
    for (int off = 1; off < 32; off <<= 1) {
        int u = __shfl_up_sync(0xFFFFFFFFu, incl, off);
        if (lane >= off) incl += u;
    }
    if (lane == 31) wsc[wid] = incl;
    __syncthreads();
    if (wid == 0) {
        int ws = (lane < 8) ? wsc[lane] : 0;
        #pragma unroll
        for (int off = 1; off < 8; off <<= 1) {
            int u = __shfl_up_sync(0xFFFFFFFFu, ws, off);
            if (lane >= off) ws += u;
        }
        if (lane < 8) wsc[lane] = ws;
    }
    __syncthreads();
    int excl = incl - v + (wid ? wsc[wid - 1] : 0) + g_bsum[blockIdx.x];
    if (i < NNODES) {
        g_rowptr[i] = excl;
        g_cursor[i] = excl;
        g_cnt[i] = 0;
    }
}
__global__ void scatter_kernel(const int* __restrict__ src, const int* __restrict__ dst,
                               const float* __restrict__ sw, const float* __restrict__ pw,
                               int E) {
    int i = blockIdx.x * blockDim.x + threadIdx.x;
    if (i < E) {
        int d = dst[i];
        int pos = atomicAdd(&g_cursor[d], 1);
        g_edge[pos] = make_uint4((uint32_t)src[i], __float_as_uint(sw[i]),
                                 __float_as_uint(pw[i]), 0u);
    }
}

// ---------------- aggregation: warp per dst node ----------------------------
__global__ void aggregate_kernel(const float* __restrict__ h) {
    int warp = (blockIdx.x * blockDim.x + threadIdx.x) >> 5;
    int lane = threadIdx.x & 31;
    if (warp >= NNODES) return;
    int beg = g_rowptr[warp];
    int end = g_rowptr[warp + 1];
    float4 as = make_float4(0.f, 0.f, 0.f, 0.f);
    float4 ap = make_float4(0.f, 0.f, 0.f, 0.f);
    int e = beg;
    for (; e + 1 < end; e += 2) {
        uint4 e0 = g_edge[e], e1 = g_edge[e + 1];
        int   s0 = (int)e0.x, s1 = (int)e1.x;
        float sw0 = __uint_as_float(e0.y), pw0 = __uint_as_float(e0.z);
        float sw1 = __uint_as_float(e1.y), pw1 = __uint_as_float(e1.z);
        float4 h0 = *reinterpret_cast<const float4*>(&h[(size_t)s0 * DH + lane * 4]);
        float4 h1 = *reinterpret_cast<const float4*>(&h[(size_t)s1 * DH + lane * 4]);
        as.x += sw0 * h0.x; as.y += sw0 * h0.y; as.z += sw0 * h0.z; as.w += sw0 * h0.w;
        ap.x += pw0 * h0.x; ap.y += pw0 * h0.y; ap.z += pw0 * h0.z; ap.w += pw0 * h0.w;
        as.x += sw1 * h1.x; as.y += sw1 * h1.y; as.z += sw1 * h1.z; as.w += sw1 * h1.w;
        ap.x += pw1 * h1.x; ap.y += pw1 * h1.y; ap.z += pw1 * h1.z; ap.w += pw1 * h1.w;
    }
    if (e < end) {
        uint4 e0 = g_edge[e];
        int   s0 = (int)e0.x;
        float sw0 = __uint_as_float(e0.y), pw0 = __uint_as_float(e0.z);
        float4 h0 = *reinterpret_cast<const float4*>(&h[(size_t)s0 * DH + lane * 4]);
        as.x += sw0 * h0.x; as.y += sw0 * h0.y; as.z += sw0 * h0.z; as.w += sw0 * h0.w;
        ap.x += pw0 * h0.x; ap.y += pw0 * h0.y; ap.z += pw0 * h0.z; ap.w += pw0 * h0.w;
    }
    *reinterpret_cast<float4*>(&g_res[(size_t)warp * DH + lane * 4]) = as;
    *reinterpret_cast<float4*>(&g_agg[(size_t)warp * DH + lane * 4]) = ap;
}

// ---------------- bf16-split GEMM on HMMA (128x128 block) -------------------
// Block 128x128, BK=32, 16 warps (32M x 32N), double buffer + reg prefetch.
#define SA_STRIDE 80
#define SB_STRIDE 272
#define OFF_A_HI 0
#define OFF_A_LO 10240
#define OFF_B_HI 20480
#define OFF_B_LO 29184
#define BUF_SZ   37888
#define OFF_BIAS 75776
#define SM_TOTAL 76288

template<bool RELU, bool ADDRES>
__global__ __launch_bounds__(512)
void mma_gemm(const float* __restrict__ A, const float* __restrict__ B,
              const float* __restrict__ bias, const float* __restrict__ Res,
              float* __restrict__ C, int M, int K, int Nc) {
    extern __shared__ __align__(16) char smem[];
    const uint32_t sb = smem_u32(smem);
    const int tid  = threadIdx.x;
    const int wid  = tid >> 5;
    const int lane = tid & 31;
    const int rowBase = blockIdx.x * 128;
    const int colBase = blockIdx.y * 128;
    const int wm = (wid >> 2) * 32;
    const int wn = (wid & 3) * 32;
    float* bias_s = reinterpret_cast<float*>(smem + OFF_BIAS);

    if (tid < 128) {
        int gc = colBase + tid;
        bias_s[tid] = (gc < Nc) ? bias[gc] : 0.f;
    }

    float4 pa[2], pb[2];

    auto loadA = [&](int k0) {
        #pragma unroll
        for (int u = 0; u < 2; u++) {
            int it = tid + u * 512;
            int r  = it >> 3;
            int kq = (it & 7) << 2;
            int gr = rowBase + r;
            pa[u] = (gr < M) ? *reinterpret_cast<const float4*>(&A[(size_t)gr * K + k0 + kq])
                             : make_float4(0.f, 0.f, 0.f, 0.f);
        }
    };
    auto loadB = [&](int k0) {
        #pragma unroll
        for (int u = 0; u < 2; u++) {
            int it = tid + u * 512;
            int kr = it >> 5;
            int nq = (it & 31) << 2;
            int gc = colBase + nq;
            const float* Brow = &B[(size_t)(k0 + kr) * Nc];
            float4 v;
            if (gc + 3 < Nc) {
                v = *reinterpret_cast<const float4*>(&Brow[gc]);
            } else {
                v.x = (gc     < Nc) ? Brow[gc]     : 0.f;
                v.y = (gc + 1 < Nc) ? Brow[gc + 1] : 0.f;
                v.z = (gc + 2 < Nc) ? Brow[gc + 2] : 0.f;
                v.w = (gc + 3 < Nc) ? Brow[gc + 3] : 0.f;
            }
            pb[u] = v;
        }
    };
    auto storeAB = [&](int buf) {
        const int base = buf * BUF_SZ;
        #pragma unroll
        for (int u = 0; u < 2; u++) {
            int it = tid + u * 512;
            int r  = it >> 3;
            int kq = (it & 7) << 2;
            float4 v = pa[u];
            uint32_t hp01 = pack_bf2(v.x, v.y);
            uint32_t hp23 = pack_bf2(v.z, v.w);
            float hx = __uint_as_float(hp01 << 16);
            float hy = __uint_as_float(hp01 & 0xFFFF0000u);
            float hz = __uint_as_float(hp23 << 16);
            float hw = __uint_as_float(hp23 & 0xFFFF0000u);
            uint32_t lp01 = pack_bf2(v.x - hx, v.y - hy);
            uint32_t lp23 = pack_bf2(v.z - hz, v.w - hw);
            int ad = base + r * SA_STRIDE + kq * 2;
            *reinterpret_cast<uint2*>(smem + OFF_A_HI + ad) = make_uint2(hp01, hp23);
            *reinterpret_cast<uint2*>(smem + OFF_A_LO + ad) = make_uint2(lp01, lp23);
        }
        #pragma unroll
        for (int u = 0; u < 2; u++) {
            int it = tid + u * 512;
            int kr = it >> 5;
            int nq = (it & 31) << 2;
            float4 v = pb[u];
            uint32_t hp01 = pack_bf2(v.x, v.y);
            uint32_t hp23 = pack_bf2(v.z, v.w);
            float hx = __uint_as_float(hp01 << 16);
            float hy = __uint_as_float(hp01 & 0xFFFF0000u);
            float hz = __uint_as_float(hp23 << 16);
            float hw = __uint_as_float(hp23 & 0xFFFF0000u);
            uint32_t lp01 = pack_bf2(v.x - hx, v.y - hy);
            uint32_t lp23 = pack_bf2(v.z - hz, v.w - hw);
            int ad = base + kr * SB_STRIDE + nq * 2;
            *reinterpret_cast<uint2*>(smem + OFF_B_HI + ad) = make_uint2(hp01, hp23);
            *reinterpret_cast<uint2*>(smem + OFF_B_LO + ad) = make_uint2(lp01, lp23);
        }
    };

    float acc[2][4][4];
    #pragma unroll
    for (int mt = 0; mt < 2; mt++)
        #pragma unroll
        for (int nt = 0; nt < 4; nt++)
            #pragma unroll
            for (int q = 0; q < 4; q++) acc[mt][nt][q] = 0.f;

    const int nch = K >> 5;
    loadA(0); loadB(0);
    storeAB(0);
    if (nch > 1) { loadA(32); loadB(32); }
    __syncthreads();

    for (int ch = 0; ch < nch; ch++) {
        const int base = (ch & 1) * BUF_SZ;
        #pragma unroll
        for (int kk = 0; kk < 32; kk += 16) {
            uint32_t ahi[2][4], alo[2][4];
            #pragma unroll
            for (int mt = 0; mt < 2; mt++) {
                int row = wm + mt * 16 + (lane & 15);
                int col = kk + ((lane >> 4) << 3);
                uint32_t aadr = sb + OFF_A_HI + base + row * SA_STRIDE + col * 2;
                LDSM4(ahi[mt], aadr);
                LDSM4(alo[mt], aadr + (OFF_A_LO - OFF_A_HI));
            }
            #pragma unroll
            for (int g = 0; g < 2; g++) {
                int krow = kk + ((lane >> 3) & 1) * 8 + (lane & 7);
                int ncol = wn + g * 16 + ((lane >> 4) << 3);
                uint32_t badr = sb + OFF_B_HI + base + krow * SB_STRIDE + ncol * 2;
                uint32_t bh[4], bl[4];
                LDSM4T(bh, badr);
                LDSM4T(bl, badr + (OFF_B_LO - OFF_B_HI));
                #pragma unroll
                for (int half = 0; half < 2; half++) {
                    int nt = g * 2 + half;
                    #pragma unroll
                    for (int mt = 0; mt < 2; mt++) {
                        MMA16816(acc[mt][nt], ahi[mt], bh + 2 * half);
                        MMA16816(acc[mt][nt], ahi[mt], bl + 2 * half);
                        MMA16816(acc[mt][nt], alo[mt], bh + 2 * half);
                    }
                }
            }
        }
        if (ch + 1 < nch) {
            storeAB((ch + 1) & 1);
            if (ch + 2 < nch) { loadA((ch + 2) << 5); loadB((ch + 2) << 5); }
            __syncthreads();
        }
    }

    const int g4 = lane >> 2;
    const int t4 = lane & 3;
    #pragma unroll
    for (int mt = 0; mt < 2; mt++) {
        #pragma unroll
        for (int half = 0; half < 2; half++) {
            int gr = rowBase + wm + mt * 16 + g4 + half * 8;
            if (gr >= M) continue;
            #pragma unroll
            for (int nt = 0; nt < 4; nt++) {
                int cl = wn + nt * 8 + t4 * 2;
                int gc = colBase + cl;
                float v0 = acc[mt][nt][half * 2]     + bias_s[cl];
                float v1 = acc[mt][nt][half * 2 + 1] + bias_s[cl + 1];
                if (RELU) { v0 = fmaxf(v0, 0.f); v1 = fmaxf(v1, 0.f); }
                if (gc + 1 < Nc) {
                    if (ADDRES) {
                        float2 rr = *reinterpret_cast<const float2*>(&Res[(size_t)gr * Nc + gc]);
                        v0 += rr.x; v1 += rr.y;
                    }
                    *reinterpret_cast<float2*>(&C[(size_t)gr * Nc + gc]) = make_float2(v0, v1);
                } else if (gc < Nc) {
                    if (ADDRES) v0 += Res[(size_t)gr * Nc + gc];
                    C[(size_t)gr * Nc + gc] = v0;
                }
            }
        }
    }
}

// ---------------- wide out GEMM: fp16 2-term, 128x256 block -----------------
// C = (Ahi + Alo) @ fp16(B) + bias;  A split to fp16 hi/lo (A err ~2^-22),
// B single fp16 plane (err 2^-11 -> output rel err ~2e-4, under 1e-3 rail).
// 2 MMAs per k16 instead of 3: -33% MMA work on the biggest GEMM.
#define W_SA_STRIDE 80
#define W_SB_STRIDE 528
#define W_OFF_A_HI 0
#define W_OFF_A_LO 10240
#define W_OFF_B    20480
#define W_BUF_SZ   37376
#define W_OFF_BIAS 74752
#define W_SM_TOTAL 75776

__global__ __launch_bounds__(512)
void mma_gemm_wide(const float* __restrict__ A, const float* __restrict__ B,
                   const float* __restrict__ bias, float* __restrict__ C,
                   int M, int K, int Nc) {
    extern __shared__ __align__(16) char smem[];
    const uint32_t sb = smem_u32(smem);
    const int tid  = threadIdx.x;
    const int wid  = tid >> 5;
    const int lane = tid & 31;
    const int rowBase = blockIdx.x * 128;
    const int colBase = blockIdx.y * 256;
    const int wm = (wid & 3) * 32;     // 4 warp rows
    const int wn = (wid >> 2) * 64;    // 4 warp cols x 64
    float* bias_s = reinterpret_cast<float*>(smem + W_OFF_BIAS);

    if (tid < 256) {
        int gc = colBase + tid;
        bias_s[tid] = (gc < Nc) ? bias[gc] : 0.f;
    }

    float4 pa[2], pb[4];

    auto loadA = [&](int k0) {
        #pragma unroll
        for (int u = 0; u < 2; u++) {
            int it = tid + u * 512;          // 1024: r=it>>3, kq=(it&7)*4
            int r  = it >> 3;
            int kq = (it & 7) << 2;
            int gr = rowBase + r;
            pa[u] = (gr < M) ? *reinterpret_cast<const float4*>(&A[(size_t)gr * K + k0 + kq])
                             : make_float4(0.f, 0.f, 0.f, 0.f);
        }
    };
    auto loadB = [&](int k0) {
        #pragma unroll
        for (int u = 0; u < 4; u++) {
            int it = tid + u * 512;          // 2048: kr=it>>6, nq=(it&63)*4
            int kr = it >> 6;
            int nq = (it & 63) << 2;
            int gc = colBase + nq;
            const float* Brow = &B[(size_t)(k0 + kr) * Nc];
            float4 v;
            if (gc + 3 < Nc) {
                v = *reinterpret_cast<const float4*>(&Brow[gc]);
            } else {
                v.x = (gc     < Nc) ? Brow[gc]     : 0.f;
                v.y = (gc + 1 < Nc) ? Brow[gc + 1] : 0.f;
                v.z = (gc + 2 < Nc) ? Brow[gc + 2] : 0.f;
                v.w = (gc + 3 < Nc) ? Brow[gc + 3] : 0.f;
            }
            pb[u] = v;
        }
    };
    auto storeAB = [&](int buf) {
        const int base = buf * W_BUF_SZ;
        #pragma unroll
        for (int u = 0; u < 2; u++) {
            int it = tid + u * 512;
            int r  = it >> 3;
            int kq = (it & 7) << 2;
            float4 v = pa[u];
            uint32_t hp01 = pack_h2(v.x, v.y);
            uint32_t hp23 = pack_h2(v.z, v.w);
            float2 h01 = unpack_h2(hp01);
            float2 h23 = unpack_h2(hp23);
            uint32_t lp01 = pack_h2(v.x - h01.x, v.y - h01.y);
            uint32_t lp23 = pack_h2(v.z - h23.x, v.w - h23.y);
            int ad = base + r * W_SA_STRIDE + kq * 2;
            *reinterpret_cast<uint2*>(smem + W_OFF_A_HI + ad) = make_uint2(hp01, hp23);
            *reinterpret_cast<uint2*>(smem + W_OFF_A_LO + ad) = make_uint2(lp01, lp23);
        }
        #pragma unroll
        for (int u = 0; u < 4; u++) {
            int it = tid + u * 512;
            int kr = it >> 6;
            int nq = (it & 63) << 2;
            float4 v = pb[u];
            uint32_t hp01 = pack_h2(v.x, v.y);
            uint32_t hp23 = pack_h2(v.z, v.w);
            int ad = base + kr * W_SB_STRIDE + nq * 2;
            *reinterpret_cast<uint2*>(smem + W_OFF_B + ad) = make_uint2(hp01, hp23);
        }
    };

    float acc[2][8][4];
    #pragma unroll
    for (int mt = 0; mt < 2; mt++)
        #pragma unroll
        for (int nt = 0; nt < 8; nt++)
            #pragma unroll
            for (int q = 0; q < 4; q++) acc[mt][nt][q] = 0.f;

    const int nch = K >> 5;
    loadA(0); loadB(0);
    storeAB(0);
    if (nch > 1) { loadA(32); loadB(32); }
    __syncthreads();

    for (int ch = 0; ch < nch; ch++) {
        const int base = (ch & 1) * W_BUF_SZ;
        #pragma unroll
        for (int kk = 0; kk < 32; kk += 16) {
            uint32_t ahi[2][4], alo[2][4];
            #pragma unroll
            for (int mt = 0; mt < 2; mt++) {
                int row = wm + mt * 16 + (lane & 15);
                int col = kk + ((lane >> 4) << 3);
                uint32_t aadr = sb + W_OFF_A_HI + base + row * W_SA_STRIDE + col * 2;
                LDSM4(ahi[mt], aadr);
                LDSM4(alo[mt], aadr + (W_OFF_A_LO - W_OFF_A_HI));
            }
            #pragma unroll
            for (int g = 0; g < 4; g++) {
                int krow = kk + ((lane >> 3) & 1) * 8 + (lane & 7);
                int ncol = wn + g * 16 + ((lane >> 4) << 3);
                uint32_t badr = sb + W_OFF_B + base + krow * W_SB_STRIDE + ncol * 2;
                uint32_t bh[4];
                LDSM4T(bh, badr);
                #pragma unroll
                for (int half = 0; half < 2; half++) {
                    int nt = g * 2 + half;
                    #pragma unroll
                    for (int mt = 0; mt < 2; mt++) {
                        MMA16816H(acc[mt][nt], ahi[mt], bh + 2 * half);
                        MMA16816H(acc[mt][nt], alo[mt], bh + 2 * half);
                    }
                }
            }
        }
        if (ch + 1 < nch) {
            storeAB((ch + 1) & 1);
            if (ch + 2 < nch) { loadA((ch + 2) << 5); loadB((ch + 2) << 5); }
            __syncthreads();
        }
    }

    const int g4 = lane >> 2;
    const int t4 = lane & 3;
    #pragma unroll
    for (int mt = 0; mt < 2; mt++) {
        #pragma unroll
        for (int half = 0; half < 2; half++) {
            int gr = rowBase + wm + mt * 16 + g4 + half * 8;
            if (gr >= M) continue;
            #pragma unroll
            for (int nt = 0; nt < 8; nt++) {
                int cl = wn + nt * 8 + t4 * 2;
                int gc = colBase + cl;
                float v0 = acc[mt][nt][half * 2]     + bias_s[cl];
                float v1 = acc[mt][nt][half * 2 + 1] + bias_s[cl + 1];
                if (gc + 1 < Nc) {
                    *reinterpret_cast<float2*>(&C[(size_t)gr * Nc + gc]) = make_float2(v0, v1);
                } else if (gc < Nc) {
                    C[(size_t)gr * Nc + gc] = v0;
                }
            }
        }
    }
}

// ---------------- launch ----------------------------------------------------
extern "C" void kernel_launch(void* const* d_in, const int* in_sizes, int n_in,
                              void* d_out, int out_size) {
    const float* x      = (const float*)d_in[0];
    const int*   src    = (const int*)  d_in[1];
    const int*   dst    = (const int*)  d_in[2];
    const float* self_w = (const float*)d_in[3];
    const float* ppi_w  = (const float*)d_in[4];
    const float* W_in   = (const float*)d_in[5];
    const float* b_in   = (const float*)d_in[6];
    const float* W1     = (const float*)d_in[7];
    const float* b1     = (const float*)d_in[8];
    const float* W2     = (const float*)d_in[9];
    const float* b2     = (const float*)d_in[10];
    const float* W_out  = (const float*)d_in[11];
    const float* b_out  = (const float*)d_in[12];
    float* out = (float*)d_out;
    const int E = in_sizes[1];

    float *ha, *hb, *agg, *res;
    cudaGetSymbolAddress((void**)&ha,  g_ha);
    cudaGetSymbolAddress((void**)&hb,  g_hb);
    cudaGetSymbolAddress((void**)&agg, g_agg);
    cudaGetSymbolAddress((void**)&res, g_res);

    static cudaStream_t s2 = nullptr;
    static cudaEvent_t evFork = nullptr, evJoin = nullptr;
    if (s2 == nullptr) {
        cudaStreamCreateWithFlags(&s2, cudaStreamNonBlocking);
        cudaEventCreateWithFlags(&evFork, cudaEventDisableTiming);
        cudaEventCreateWithFlags(&evJoin, cudaEventDisableTiming);
    }

    cudaFuncSetAttribute(mma_gemm<true,  false>, cudaFuncAttributeMaxDynamicSharedMemorySize, SM_TOTAL);
    cudaFuncSetAttribute(mma_gemm<true,  true >, cudaFuncAttributeMaxDynamicSharedMemorySize, SM_TOTAL);
    cudaFuncSetAttribute(mma_gemm_wide, cudaFuncAttributeMaxDynamicSharedMemorySize, W_SM_TOTAL);

    const dim3 blk(512);
    const dim3 g_h((NNODES + 127) / 128, 1);
    const dim3 g_o((NNODES + 127) / 128, (NLAB + 255) / 256);
    const int agg_blocks = (NNODES * 32 + 255) / 256;

    // fork: CSR build chain on s2, input GEMM on main stream (independent)
    cudaEventRecord(evFork, 0);
    cudaStreamWaitEvent(s2, evFork, 0);

    hist_kernel<<<(E + 255) / 256, 256, 0, s2>>>(dst, E);
    scanA_kernel<<<NSCANB, 256, 0, s2>>>();
    scanB_kernel<<<1, 256, 0, s2>>>();
    scanC_kernel<<<NSCANB, 256, 0, s2>>>();
    scatter_kernel<<<(E + 255) / 256, 256, 0, s2>>>(src, dst, self_w, ppi_w, E);
    cudaEventRecord(evJoin, s2);

    // h = relu(x @ W_in + b_in)
    mma_gemm<true, false><<<g_h, blk, SM_TOTAL>>>(x, W_in, b_in, nullptr, ha, NNODES, DIN, DH);

    cudaStreamWaitEvent(0, evJoin, 0);

    // layer 1
    aggregate_kernel<<<agg_blocks, 256>>>(ha);
    mma_gemm<true, true><<<g_h, blk, SM_TOTAL>>>(agg, W1, b1, res, hb, NNODES, DH, DH);
    // layer 2
    aggregate_kernel<<<agg_blocks, 256>>>(hb);
    mma_gemm<true, true><<<g_h, blk, SM_TOTAL>>>(agg, W2, b2, res, ha, NNODES, DH, DH);
    // out = h @ W_out + b_out  (fp16 2-term wide kernel)
    mma_gemm_wide<<<g_o, blk, W_SM_TOTAL>>>(ha, W_out, b_out, out, NNODES, DH, NLAB);
}

// round 15
// speedup vs baseline: 1.1072x; 1.0229x over previous
#include <cuda_runtime.h>
#include <cuda_bf16.h>
#include <cuda_fp16.h>
#include <cstdint>

#define NNODES 50000
#define NEDGES 800000
#define DIN    256
#define DH     128
#define NLAB   1000
#define NSCANB 196   // ceil(50000/256)

// ---------------- scratch (static device allocations; no cudaMalloc) --------
__device__ float g_ha[NNODES * DH];
__device__ float g_hb[NNODES * DH];
__device__ float g_agg[NNODES * DH];
__device__ float g_res[NNODES * DH];
__device__ int   g_cnt[NNODES];          // zero-init; left zero after each call
__device__ int   g_rowptr[NNODES + 1];
__device__ int   g_cursor[NNODES];
__device__ int   g_bsum[NSCANB];
__device__ uint4 g_edge[NEDGES];         // {src, self_w, ppi_w, pad} AoS

// ---------------- helpers ----------------------------------------------------
__device__ __forceinline__ uint32_t smem_u32(const void* p) {
    uint32_t a;
    asm("{ .reg .u64 t; cvta.to.shared.u64 t, %1; cvt.u32.u64 %0, t; }" : "=r"(a) : "l"(p));
    return a;
}
__device__ __forceinline__ uint32_t pack_bf2(float e0, float e1) {
    // low half = bf16(e0), high half = bf16(e1)
    uint32_t r;
    asm("cvt.rn.satfinite.bf16x2.f32 %0, %1, %2;" : "=r"(r) : "f"(e1), "f"(e0));
    return r;
}
__device__ __forceinline__ uint32_t pack_h2(float e0, float e1) {
    __half2 h = __floats2half2_rn(e0, e1);   // e0 -> low
    return *reinterpret_cast<uint32_t*>(&h);
}
__device__ __forceinline__ float2 unpack_h2(uint32_t u) {
    __half2 h = *reinterpret_cast<__half2*>(&u);
    return __half22float2(h);
}

#define LDSM4(r, addr)                                                          \
    asm volatile("ldmatrix.sync.aligned.m8n8.x4.shared.b16 {%0,%1,%2,%3}, [%4];"\
        : "=r"((r)[0]), "=r"((r)[1]), "=r"((r)[2]), "=r"((r)[3]) : "r"(addr))
#define LDSM4T(r, addr)                                                         \
    asm volatile("ldmatrix.sync.aligned.m8n8.x4.trans.shared.b16 {%0,%1,%2,%3}, [%4];"\
        : "=r"((r)[0]), "=r"((r)[1]), "=r"((r)[2]), "=r"((r)[3]) : "r"(addr))
#define MMA16816(d, a, b)                                                       \
    asm volatile("mma.sync.aligned.m16n8k16.row.col.f32.bf16.bf16.f32 "         \
        "{%0,%1,%2,%3}, {%4,%5,%6,%7}, {%8,%9}, {%0,%1,%2,%3};"                 \
        : "+f"((d)[0]), "+f"((d)[1]), "+f"((d)[2]), "+f"((d)[3])                \
        : "r"((a)[0]), "r"((a)[1]), "r"((a)[2]), "r"((a)[3]),                   \
          "r"((b)[0]), "r"((b)[1]))
#define MMA16816H(d, a, b)                                                      \
    asm volatile("mma.sync.aligned.m16n8k16.row.col.f32.f16.f16.f32 "           \
        "{%0,%1,%2,%3}, {%4,%5,%6,%7}, {%8,%9}, {%0,%1,%2,%3};"                 \
        : "+f"((d)[0]), "+f"((d)[1]), "+f"((d)[2]), "+f"((d)[3])                \
        : "r"((a)[0]), "r"((a)[1]), "r"((a)[2]), "r"((a)[3]),                   \
          "r"((b)[0]), "r"((b)[1]))

// ---------------- CSR build -------------------------------------------------
__global__ void hist_kernel(const int* __restrict__ dst, int E) {
    int i = blockIdx.x * blockDim.x + threadIdx.x;
    if (i < E) atomicAdd(&g_cnt[dst[i]], 1);
}
__global__ void scanA_kernel() {
    __shared__ int wsum[8];
    int i = blockIdx.x * 256 + threadIdx.x;
    int lane = threadIdx.x & 31, wid = threadIdx.x >> 5;
    int v = (i < NNODES) ? g_cnt[i] : 0;
    #pragma unroll
    for (int off = 16; off > 0; off >>= 1) v += __shfl_down_sync(0xFFFFFFFFu, v, off);
    if (lane == 0) wsum[wid] = v;
    __syncthreads();
    if (threadIdx.x == 0) {
        int s = 0;
        #pragma unroll
        for (int w = 0; w < 8; w++) s += wsum[w];
        g_bsum[blockIdx.x] = s;
    }
}
__global__ void scanB_kernel() {
    __shared__ int wsc[8];
    int t = threadIdx.x;
    int lane = t & 31, wid = t >> 5;
    int v = (t < NSCANB) ? g_bsum[t] : 0;
    int incl = v;
    #pragma unroll
    for (int off = 1; off < 32; off <<= 1) {
        int u = __shfl_up_sync(0xFFFFFFFFu, incl, off);
        if (lane >= off) incl += u;
    }
    if (lane == 31) wsc[wid] = incl;
    __syncthreads();
    if (wid == 0) {
        int ws = (lane < 8) ? wsc[lane] : 0;
        #pragma unroll
        for (int off = 1; off < 8; off <<= 1) {
            int u = __shfl_up_sync(0xFFFFFFFFu, ws, off);
            if (lane >= off) ws += u;
        }
        if (lane < 8) wsc[lane] = ws;
    }
    __syncthreads();
    int excl = incl - v + (wid ? wsc[wid - 1] : 0);
    if (t < NSCANB) g_bsum[t] = excl;
    if (t == 255) g_rowptr[NNODES] = excl + v;
}
__global__ void scanC_kernel() {
    __shared__ int wsc[8];
    int i = blockIdx.x * 256 + threadIdx.x;
    int t = threadIdx.x, lane = t & 31, wid = t >> 5;
    int v = (i < NNODES) ? g_cnt[i] : 0;
    int incl = v;
    #pragma unroll
    for (int off = 1; off < 32; off <<= 1) {
        int u = __shfl_up_sync(0xFFFFFFFFu, incl, off);
        if (lane >= off) incl += u;
    }
    if (lane == 31) wsc[wid] = incl;
    __syncthreads();
    if (wid == 0) {
        int ws = (lane < 8) ? wsc[lane] : 0;
        #pragma unroll
        for (int off = 1; off < 8; off <<= 1) {
            int u = __shfl_up_sync(0xFFFFFFFFu, ws, off);
            if (lane >= off) ws += u;
        }
        if (lane < 8) wsc[lane] = ws;
    }
    __syncthreads();
    int excl = incl - v + (wid ? wsc[wid - 1] : 0) + g_bsum[blockIdx.x];
    if (i < NNODES) {
        g_rowptr[i] = excl;
        g_cursor[i] = excl;
        g_cnt[i] = 0;
    }
}
__global__ void scatter_kernel(const int* __restrict__ src, const int* __restrict__ dst,
                               const float* __restrict__ sw, const float* __restrict__ pw,
                               int E) {
    int i = blockIdx.x * blockDim.x + threadIdx.x;
    if (i < E) {
        int d = dst[i];
        int pos = atomicAdd(&g_cursor[d], 1);
        g_edge[pos] = make_uint4((uint32_t)src[i], __float_as_uint(sw[i]),
                                 __float_as_uint(pw[i]), 0u);
    }
}

// ---------------- aggregation: warp per dst node ----------------------------
__global__ void aggregate_kernel(const float* __restrict__ h) {
    int warp = (blockIdx.x * blockDim.x + threadIdx.x) >> 5;
    int lane = threadIdx.x & 31;
    if (warp >= NNODES) return;
    int beg = g_rowptr[warp];
    int end = g_rowptr[warp + 1];
    float4 as = make_float4(0.f, 0.f, 0.f, 0.f);
    float4 ap = make_float4(0.f, 0.f, 0.f, 0.f);
    int e = beg;
    for (; e + 1 < end; e += 2) {
        uint4 e0 = g_edge[e], e1 = g_edge[e + 1];
        int   s0 = (int)e0.x, s1 = (int)e1.x;
        float sw0 = __uint_as_float(e0.y), pw0 = __uint_as_float(e0.z);
        float sw1 = __uint_as_float(e1.y), pw1 = __uint_as_float(e1.z);
        float4 h0 = *reinterpret_cast<const float4*>(&h[(size_t)s0 * DH + lane * 4]);
        float4 h1 = *reinterpret_cast<const float4*>(&h[(size_t)s1 * DH + lane * 4]);
        as.x += sw0 * h0.x; as.y += sw0 * h0.y; as.z += sw0 * h0.z; as.w += sw0 * h0.w;
        ap.x += pw0 * h0.x; ap.y += pw0 * h0.y; ap.z += pw0 * h0.z; ap.w += pw0 * h0.w;
        as.x += sw1 * h1.x; as.y += sw1 * h1.y; as.z += sw1 * h1.z; as.w += sw1 * h1.w;
        ap.x += pw1 * h1.x; ap.y += pw1 * h1.y; ap.z += pw1 * h1.z; ap.w += pw1 * h1.w;
    }
    if (e < end) {
        uint4 e0 = g_edge[e];
        int   s0 = (int)e0.x;
        float sw0 = __uint_as_float(e0.y), pw0 = __uint_as_float(e0.z);
        float4 h0 = *reinterpret_cast<const float4*>(&h[(size_t)s0 * DH + lane * 4]);
        as.x += sw0 * h0.x; as.y += sw0 * h0.y; as.z += sw0 * h0.z; as.w += sw0 * h0.w;
        ap.x += pw0 * h0.x; ap.y += pw0 * h0.y; ap.z += pw0 * h0.z; ap.w += pw0 * h0.w;
    }
    *reinterpret_cast<float4*>(&g_res[(size_t)warp * DH + lane * 4]) = as;
    *reinterpret_cast<float4*>(&g_agg[(size_t)warp * DH + lane * 4]) = ap;
}

// ---------------- bf16-split GEMM on HMMA (128x128 block, 3-term) -----------
// Used only for the input GEMM (keeps full precision headroom; runs
// concurrently with the CSR chain so its duration is not critical-path).
#define SA_STRIDE 80
#define SB_STRIDE 272
#define OFF_A_HI 0
#define OFF_A_LO 10240
#define OFF_B_HI 20480
#define OFF_B_LO 29184
#define BUF_SZ   37888
#define OFF_BIAS 75776
#define SM_TOTAL 76288

template<bool RELU, bool ADDRES>
__global__ __launch_bounds__(512)
void mma_gemm(const float* __restrict__ A, const float* __restrict__ B,
              const float* __restrict__ bias, const float* __restrict__ Res,
              float* __restrict__ C, int M, int K, int Nc) {
    extern __shared__ __align__(16) char smem[];
    const uint32_t sb = smem_u32(smem);
    const int tid  = threadIdx.x;
    const int wid  = tid >> 5;
    const int lane = tid & 31;
    const int rowBase = blockIdx.x * 128;
    const int colBase = blockIdx.y * 128;
    const int wm = (wid >> 2) * 32;
    const int wn = (wid & 3) * 32;
    float* bias_s = reinterpret_cast<float*>(smem + OFF_BIAS);

    if (tid < 128) {
        int gc = colBase + tid;
        bias_s[tid] = (gc < Nc) ? bias[gc] : 0.f;
    }

    float4 pa[2], pb[2];

    auto loadA = [&](int k0) {
        #pragma unroll
        for (int u = 0; u < 2; u++) {
            int it = tid + u * 512;
            int r  = it >> 3;
            int kq = (it & 7) << 2;
            int gr = rowBase + r;
            pa[u] = (gr < M) ? *reinterpret_cast<const float4*>(&A[(size_t)gr * K + k0 + kq])
                             : make_float4(0.f, 0.f, 0.f, 0.f);
        }
    };
    auto loadB = [&](int k0) {
        #pragma unroll
        for (int u = 0; u < 2; u++) {
            int it = tid + u * 512;
            int kr = it >> 5;
            int nq = (it & 31) << 2;
            int gc = colBase + nq;
            const float* Brow = &B[(size_t)(k0 + kr) * Nc];
            float4 v;
            if (gc + 3 < Nc) {
                v = *reinterpret_cast<const float4*>(&Brow[gc]);
            } else {
                v.x = (gc     < Nc) ? Brow[gc]     : 0.f;
                v.y = (gc + 1 < Nc) ? Brow[gc + 1] : 0.f;
                v.z = (gc + 2 < Nc) ? Brow[gc + 2] : 0.f;
                v.w = (gc + 3 < Nc) ? Brow[gc + 3] : 0.f;
            }
            pb[u] = v;
        }
    };
    auto storeAB = [&](int buf) {
        const int base = buf * BUF_SZ;
        #pragma unroll
        for (int u = 0; u < 2; u++) {
            int it = tid + u * 512;
            int r  = it >> 3;
            int kq = (it & 7) << 2;
            float4 v = pa[u];
            uint32_t hp01 = pack_bf2(v.x, v.y);
            uint32_t hp23 = pack_bf2(v.z, v.w);
            float hx = __uint_as_float(hp01 << 16);
            float hy = __uint_as_float(hp01 & 0xFFFF0000u);
            float hz = __uint_as_float(hp23 << 16);
            float hw = __uint_as_float(hp23 & 0xFFFF0000u);
            uint32_t lp01 = pack_bf2(v.x - hx, v.y - hy);
            uint32_t lp23 = pack_bf2(v.z - hz, v.w - hw);
            int ad = base + r * SA_STRIDE + kq * 2;
            *reinterpret_cast<uint2*>(smem + OFF_A_HI + ad) = make_uint2(hp01, hp23);
            *reinterpret_cast<uint2*>(smem + OFF_A_LO + ad) = make_uint2(lp01, lp23);
        }
        #pragma unroll
        for (int u = 0; u < 2; u++) {
            int it = tid + u * 512;
            int kr = it >> 5;
            int nq = (it & 31) << 2;
            float4 v = pb[u];
            uint32_t hp01 = pack_bf2(v.x, v.y);
            uint32_t hp23 = pack_bf2(v.z, v.w);
            float hx = __uint_as_float(hp01 << 16);
            float hy = __uint_as_float(hp01 & 0xFFFF0000u);
            float hz = __uint_as_float(hp23 << 16);
            float hw = __uint_as_float(hp23 & 0xFFFF0000u);
            uint32_t lp01 = pack_bf2(v.x - hx, v.y - hy);
            uint32_t lp23 = pack_bf2(v.z - hz, v.w - hw);
            int ad = base + kr * SB_STRIDE + nq * 2;
            *reinterpret_cast<uint2*>(smem + OFF_B_HI + ad) = make_uint2(hp01, hp23);
            *reinterpret_cast<uint2*>(smem + OFF_B_LO + ad) = make_uint2(lp01, lp23);
        }
    };

    float acc[2][4][4];
    #pragma unroll
    for (int mt = 0; mt < 2; mt++)
        #pragma unroll
        for (int nt = 0; nt < 4; nt++)
            #pragma unroll
            for (int q = 0; q < 4; q++) acc[mt][nt][q] = 0.f;

    const int nch = K >> 5;
    loadA(0); loadB(0);
    storeAB(0);
    if (nch > 1) { loadA(32); loadB(32); }
    __syncthreads();

    for (int ch = 0; ch < nch; ch++) {
        const int base = (ch & 1) * BUF_SZ;
        #pragma unroll
        for (int kk = 0; kk < 32; kk += 16) {
            uint32_t ahi[2][4], alo[2][4];
            #pragma unroll
            for (int mt = 0; mt < 2; mt++) {
                int row = wm + mt * 16 + (lane & 15);
                int col = kk + ((lane >> 4) << 3);
                uint32_t aadr = sb + OFF_A_HI + base + row * SA_STRIDE + col * 2;
                LDSM4(ahi[mt], aadr);
                LDSM4(alo[mt], aadr + (OFF_A_LO - OFF_A_HI));
            }
            #pragma unroll
            for (int g = 0; g < 2; g++) {
                int krow = kk + ((lane >> 3) & 1) * 8 + (lane & 7);
                int ncol = wn + g * 16 + ((lane >> 4) << 3);
                uint32_t badr = sb + OFF_B_HI + base + krow * SB_STRIDE + ncol * 2;
                uint32_t bh[4], bl[4];
                LDSM4T(bh, badr);
                LDSM4T(bl, badr + (OFF_B_LO - OFF_B_HI));
                #pragma unroll
                for (int half = 0; half < 2; half++) {
                    int nt = g * 2 + half;
                    #pragma unroll
                    for (int mt = 0; mt < 2; mt++) {
                        MMA16816(acc[mt][nt], ahi[mt], bh + 2 * half);
                        MMA16816(acc[mt][nt], ahi[mt], bl + 2 * half);
                        MMA16816(acc[mt][nt], alo[mt], bh + 2 * half);
                    }
                }
            }
        }
        if (ch + 1 < nch) {
            storeAB((ch + 1) & 1);
            if (ch + 2 < nch) { loadA((ch + 2) << 5); loadB((ch + 2) << 5); }
            __syncthreads();
        }
    }

    const int g4 = lane >> 2;
    const int t4 = lane & 3;
    #pragma unroll
    for (int mt = 0; mt < 2; mt++) {
        #pragma unroll
        for (int half = 0; half < 2; half++) {
            int gr = rowBase + wm + mt * 16 + g4 + half * 8;
            if (gr >= M) continue;
            #pragma unroll
            for (int nt = 0; nt < 4; nt++) {
                int cl = wn + nt * 8 + t4 * 2;
                int gc = colBase + cl;
                float v0 = acc[mt][nt][half * 2]     + bias_s[cl];
                float v1 = acc[mt][nt][half * 2 + 1] + bias_s[cl + 1];
                if (RELU) { v0 = fmaxf(v0, 0.f); v1 = fmaxf(v1, 0.f); }
                if (gc + 1 < Nc) {
                    if (ADDRES) {
                        float2 rr = *reinterpret_cast<const float2*>(&Res[(size_t)gr * Nc + gc]);
                        v0 += rr.x; v1 += rr.y;
                    }
                    *reinterpret_cast<float2*>(&C[(size_t)gr * Nc + gc]) = make_float2(v0, v1);
                } else if (gc < Nc) {
                    if (ADDRES) v0 += Res[(size_t)gr * Nc + gc];
                    C[(size_t)gr * Nc + gc] = v0;
                }
            }
        }
    }
}

// ---------------- fp16 2-term GEMM (128x128 block) for mid layers -----------
// C = (Ahi + Alo) @ fp16(B) + bias [+Res], relu.  A err ~2^-22, B err 2^-11.
// 16 MMAs per warp-chunk instead of 24; one B plane instead of two.
#define F_OFF_A_HI 0
#define F_OFF_A_LO 10240
#define F_OFF_B    20480
#define F_BUF_SZ   29184
#define F_OFF_BIAS 58368
#define F_SM_TOTAL 58880

template<bool RELU, bool ADDRES>
__global__ __launch_bounds__(512)
void mma_gemm_f16(const float* __restrict__ A, const float* __restrict__ B,
                  const float* __restrict__ bias, const float* __restrict__ Res,
                  float* __restrict__ C, int M, int K, int Nc) {
    extern __shared__ __align__(16) char smem[];
    const uint32_t sb = smem_u32(smem);
    const int tid  = threadIdx.x;
    const int wid  = tid >> 5;
    const int lane = tid & 31;
    const int rowBase = blockIdx.x * 128;
    const int colBase = blockIdx.y * 128;
    const int wm = (wid >> 2) * 32;
    const int wn = (wid & 3) * 32;
    float* bias_s = reinterpret_cast<float*>(smem + F_OFF_BIAS);

    if (tid < 128) {
        int gc = colBase + tid;
        bias_s[tid] = (gc < Nc) ? bias[gc] : 0.f;
    }

    float4 pa[2], pb[2];

    auto loadA = [&](int k0) {
        #pragma unroll
        for (int u = 0; u < 2; u++) {
            int it = tid + u * 512;
            int r  = it >> 3;
            int kq = (it & 7) << 2;
            int gr = rowBase + r;
            pa[u] = (gr < M) ? *reinterpret_cast<const float4*>(&A[(size_t)gr * K + k0 + kq])
                             : make_float4(0.f, 0.f, 0.f, 0.f);
        }
    };
    auto loadB = [&](int k0) {
        #pragma unroll
        for (int u = 0; u < 2; u++) {
            int it = tid + u * 512;
            int kr = it >> 5;
            int nq = (it & 31) << 2;
            int gc = colBase + nq;
            const float* Brow = &B[(size_t)(k0 + kr) * Nc];
            float4 v;
            if (gc + 3 < Nc) {
                v = *reinterpret_cast<const float4*>(&Brow[gc]);
            } else {
                v.x = (gc     < Nc) ? Brow[gc]     : 0.f;
                v.y = (gc + 1 < Nc) ? Brow[gc + 1] : 0.f;
                v.z = (gc + 2 < Nc) ? Brow[gc + 2] : 0.f;
                v.w = (gc + 3 < Nc) ? Brow[gc + 3] : 0.f;
            }
            pb[u] = v;
        }
    };
    auto storeAB = [&](int buf) {
        const int base = buf * F_BUF_SZ;
        #pragma unroll
        for (int u = 0; u < 2; u++) {
            int it = tid + u * 512;
            int r  = it >> 3;
            int kq = (it & 7) << 2;
            float4 v = pa[u];
            uint32_t hp01 = pack_h2(v.x, v.y);
            uint32_t hp23 = pack_h2(v.z, v.w);
            float2 h01 = unpack_h2(hp01);
            float2 h23 = unpack_h2(hp23);
            uint32_t lp01 = pack_h2(v.x - h01.x, v.y - h01.y);
            uint32_t lp23 = pack_h2(v.z - h23.x, v.w - h23.y);
            int ad = base + r * SA_STRIDE + kq * 2;
            *reinterpret_cast<uint2*>(smem + F_OFF_A_HI + ad) = make_uint2(hp01, hp23);
            *reinterpret_cast<uint2*>(smem + F_OFF_A_LO + ad) = make_uint2(lp01, lp23);
        }
        #pragma unroll
        for (int u = 0; u < 2; u++) {
            int it = tid + u * 512;
            int kr = it >> 5;
            int nq = (it & 31) << 2;
            float4 v = pb[u];
            uint32_t hp01 = pack_h2(v.x, v.y);
            uint32_t hp23 = pack_h2(v.z, v.w);
            int ad = base + kr * SB_STRIDE + nq * 2;
            *reinterpret_cast<uint2*>(smem + F_OFF_B + ad) = make_uint2(hp01, hp23);
        }
    };

    float acc[2][4][4];
    #pragma unroll
    for (int mt = 0; mt < 2; mt++)
        #pragma unroll
        for (int nt = 0; nt < 4; nt++)
            #pragma unroll
            for (int q = 0; q < 4; q++) acc[mt][nt][q] = 0.f;

    const int nch = K >> 5;
    loadA(0); loadB(0);
    storeAB(0);
    if (nch > 1) { loadA(32); loadB(32); }
    __syncthreads();

    for (int ch = 0; ch < nch; ch++) {
        const int base = (ch & 1) * F_BUF_SZ;
        #pragma unroll
        for (int kk = 0; kk < 32; kk += 16) {
            uint32_t ahi[2][4], alo[2][4];
            #pragma unroll
            for (int mt = 0; mt < 2; mt++) {
                int row = wm + mt * 16 + (lane & 15);
                int col = kk + ((lane >> 4) << 3);
                uint32_t aadr = sb + F_OFF_A_HI + base + row * SA_STRIDE + col * 2;
                LDSM4(ahi[mt], aadr);
                LDSM4(alo[mt], aadr + (F_OFF_A_LO - F_OFF_A_HI));
            }
            #pragma unroll
            for (int g = 0; g < 2; g++) {
                int krow = kk + ((lane >> 3) & 1) * 8 + (lane & 7);
                int ncol = wn + g * 16 + ((lane >> 4) << 3);
                uint32_t badr = sb + F_OFF_B + base + krow * SB_STRIDE + ncol * 2;
                uint32_t bh[4];
                LDSM4T(bh, badr);
                #pragma unroll
                for (int half = 0; half < 2; half++) {
                    int nt = g * 2 + half;
                    #pragma unroll
                    for (int mt = 0; mt < 2; mt++) {
                        MMA16816H(acc[mt][nt], ahi[mt], bh + 2 * half);
                        MMA16816H(acc[mt][nt], alo[mt], bh + 2 * half);
                    }
                }
            }
        }
        if (ch + 1 < nch) {
            storeAB((ch + 1) & 1);
            if (ch + 2 < nch) { loadA((ch + 2) << 5); loadB((ch + 2) << 5); }
            __syncthreads();
        }
    }

    const int g4 = lane >> 2;
    const int t4 = lane & 3;
    #pragma unroll
    for (int mt = 0; mt < 2; mt++) {
        #pragma unroll
        for (int half = 0; half < 2; half++) {
            int gr = rowBase + wm + mt * 16 + g4 + half * 8;
            if (gr >= M) continue;
            #pragma unroll
            for (int nt = 0; nt < 4; nt++) {
                int cl = wn + nt * 8 + t4 * 2;
                int gc = colBase + cl;
                float v0 = acc[mt][nt][half * 2]     + bias_s[cl];
                float v1 = acc[mt][nt][half * 2 + 1] + bias_s[cl + 1];
                if (RELU) { v0 = fmaxf(v0, 0.f); v1 = fmaxf(v1, 0.f); }
                if (gc + 1 < Nc) {
                    if (ADDRES) {
                        float2 rr = *reinterpret_cast<const float2*>(&Res[(size_t)gr * Nc + gc]);
                        v0 += rr.x; v1 += rr.y;
                    }
                    *reinterpret_cast<float2*>(&C[(size_t)gr * Nc + gc]) = make_float2(v0, v1);
                } else if (gc < Nc) {
                    if (ADDRES) v0 += Res[(size_t)gr * Nc + gc];
                    C[(size_t)gr * Nc + gc] = v0;
                }
            }
        }
    }
}

// ---------------- wide out GEMM: fp16 2-term, 128x256 block -----------------
#define W_SA_STRIDE 80
#define W_SB_STRIDE 528
#define W_OFF_A_HI 0
#define W_OFF_A_LO 10240
#define W_OFF_B    20480
#define W_BUF_SZ   37376
#define W_OFF_BIAS 74752
#define W_SM_TOTAL 75776

__global__ __launch_bounds__(512)
void mma_gemm_wide(const float* __restrict__ A, const float* __restrict__ B,
                   const float* __restrict__ bias, float* __restrict__ C,
                   int M, int K, int Nc) {
    extern __shared__ __align__(16) char smem[];
    const uint32_t sb = smem_u32(smem);
    const int tid  = threadIdx.x;
    const int wid  = tid >> 5;
    const int lane = tid & 31;
    const int rowBase = blockIdx.x * 128;
    const int colBase = blockIdx.y * 256;
    const int wm = (wid & 3) * 32;
    const int wn = (wid >> 2) * 64;
    float* bias_s = reinterpret_cast<float*>(smem + W_OFF_BIAS);

    if (tid < 256) {
        int gc = colBase + tid;
        bias_s[tid] = (gc < Nc) ? bias[gc] : 0.f;
    }

    float4 pa[2], pb[4];

    auto loadA = [&](int k0) {
        #pragma unroll
        for (int u = 0; u < 2; u++) {
            int it = tid + u * 512;
            int r  = it >> 3;
            int kq = (it & 7) << 2;
            int gr = rowBase + r;
            pa[u] = (gr < M) ? *reinterpret_cast<const float4*>(&A[(size_t)gr * K + k0 + kq])
                             : make_float4(0.f, 0.f, 0.f, 0.f);
        }
    };
    auto loadB = [&](int k0) {
        #pragma unroll
        for (int u = 0; u < 4; u++) {
            int it = tid + u * 512;
            int kr = it >> 6;
            int nq = (it & 63) << 2;
            int gc = colBase + nq;
            const float* Brow = &B[(size_t)(k0 + kr) * Nc];
            float4 v;
            if (gc + 3 < Nc) {
                v = *reinterpret_cast<const float4*>(&Brow[gc]);
            } else {
                v.x = (gc     < Nc) ? Brow[gc]     : 0.f;
                v.y = (gc + 1 < Nc) ? Brow[gc + 1] : 0.f;
                v.z = (gc + 2 < Nc) ? Brow[gc + 2] : 0.f;
                v.w = (gc + 3 < Nc) ? Brow[gc + 3] : 0.f;
            }
            pb[u] = v;
        }
    };
    auto storeAB = [&](int buf) {
        const int base = buf * W_BUF_SZ;
        #pragma unroll
        for (int u = 0; u < 2; u++) {
            int it = tid + u * 512;
            int r  = it >> 3;
            int kq = (it & 7) << 2;
            float4 v = pa[u];
            uint32_t hp01 = pack_h2(v.x, v.y);
            uint32_t hp23 = pack_h2(v.z, v.w);
            float2 h01 = unpack_h2(hp01);
            float2 h23 = unpack_h2(hp23);
            uint32_t lp01 = pack_h2(v.x - h01.x, v.y - h01.y);
            uint32_t lp23 = pack_h2(v.z - h23.x, v.w - h23.y);
            int ad = base + r * W_SA_STRIDE + kq * 2;
            *reinterpret_cast<uint2*>(smem + W_OFF_A_HI + ad) = make_uint2(hp01, hp23);
            *reinterpret_cast<uint2*>(smem + W_OFF_A_LO + ad) = make_uint2(lp01, lp23);
        }
        #pragma unroll
        for (int u = 0; u < 4; u++) {
            int it = tid + u * 512;
            int kr = it >> 6;
            int nq = (it & 63) << 2;
            float4 v = pb[u];
            uint32_t hp01 = pack_h2(v.x, v.y);
            uint32_t hp23 = pack_h2(v.z, v.w);
            int ad = base + kr * W_SB_STRIDE + nq * 2;
            *reinterpret_cast<uint2*>(smem + W_OFF_B + ad) = make_uint2(hp01, hp23);
        }
    };

    float acc[2][8][4];
    #pragma unroll
    for (int mt = 0; mt < 2; mt++)
        #pragma unroll
        for (int nt = 0; nt < 8; nt++)
            #pragma unroll
            for (int q = 0; q < 4; q++) acc[mt][nt][q] = 0.f;

    const int nch = K >> 5;
    loadA(0); loadB(0);
    storeAB(0);
    if (nch > 1) { loadA(32); loadB(32); }
    __syncthreads();

    for (int ch = 0; ch < nch; ch++) {
        const int base = (ch & 1) * W_BUF_SZ;
        #pragma unroll
        for (int kk = 0; kk < 32; kk += 16) {
            uint32_t ahi[2][4], alo[2][4];
            #pragma unroll
            for (int mt = 0; mt < 2; mt++) {
                int row = wm + mt * 16 + (lane & 15);
                int col = kk + ((lane >> 4) << 3);
                uint32_t aadr = sb + W_OFF_A_HI + base + row * W_SA_STRIDE + col * 2;
                LDSM4(ahi[mt], aadr);
                LDSM4(alo[mt], aadr + (W_OFF_A_LO - W_OFF_A_HI));
            }
            #pragma unroll
            for (int g = 0; g < 4; g++) {
                int krow = kk + ((lane >> 3) & 1) * 8 + (lane & 7);
                int ncol = wn + g * 16 + ((lane >> 4) << 3);
                uint32_t badr = sb + W_OFF_B + base + krow * W_SB_STRIDE + ncol * 2;
                uint32_t bh[4];
                LDSM4T(bh, badr);
                #pragma unroll
                for (int half = 0; half < 2; half++) {
                    int nt = g * 2 + half;
                    #pragma unroll
                    for (int mt = 0; mt < 2; mt++) {
                        MMA16816H(acc[mt][nt], ahi[mt], bh + 2 * half);
                        MMA16816H(acc[mt][nt], alo[mt], bh + 2 * half);
                    }
                }
            }
        }
        if (ch + 1 < nch) {
            storeAB((ch + 1) & 1);
            if (ch + 2 < nch) { loadA((ch + 2) << 5); loadB((ch + 2) << 5); }
            __syncthreads();
        }
    }

    const int g4 = lane >> 2;
    const int t4 = lane & 3;
    #pragma unroll
    for (int mt = 0; mt < 2; mt++) {
        #pragma unroll
        for (int half = 0; half < 2; half++) {
            int gr = rowBase + wm + mt * 16 + g4 + half * 8;
            if (gr >= M) continue;
            #pragma unroll
            for (int nt = 0; nt < 8; nt++) {
                int cl = wn + nt * 8 + t4 * 2;
                int gc = colBase + cl;
                float v0 = acc[mt][nt][half * 2]     + bias_s[cl];
                float v1 = acc[mt][nt][half * 2 + 1] + bias_s[cl + 1];
                if (gc + 1 < Nc) {
                    *reinterpret_cast<float2*>(&C[(size_t)gr * Nc + gc]) = make_float2(v0, v1);
                } else if (gc < Nc) {
                    C[(size_t)gr * Nc + gc] = v0;
                }
            }
        }
    }
}

// ---------------- launch ----------------------------------------------------
extern "C" void kernel_launch(void* const* d_in, const int* in_sizes, int n_in,
                              void* d_out, int out_size) {
    const float* x      = (const float*)d_in[0];
    const int*   src    = (const int*)  d_in[1];
    const int*   dst    = (const int*)  d_in[2];
    const float* self_w = (const float*)d_in[3];
    const float* ppi_w  = (const float*)d_in[4];
    const float* W_in   = (const float*)d_in[5];
    const float* b_in   = (const float*)d_in[6];
    const float* W1     = (const float*)d_in[7];
    const float* b1     = (const float*)d_in[8];
    const float* W2     = (const float*)d_in[9];
    const float* b2     = (const float*)d_in[10];
    const float* W_out  = (const float*)d_in[11];
    const float* b_out  = (const float*)d_in[12];
    float* out = (float*)d_out;
    const int E = in_sizes[1];

    float *ha, *hb, *agg, *res;
    cudaGetSymbolAddress((void**)&ha,  g_ha);
    cudaGetSymbolAddress((void**)&hb,  g_hb);
    cudaGetSymbolAddress((void**)&agg, g_agg);
    cudaGetSymbolAddress((void**)&res, g_res);

    static cudaStream_t s2 = nullptr;
    static cudaEvent_t evFork = nullptr, evJoin = nullptr;
    if (s2 == nullptr) {
        cudaStreamCreateWithFlags(&s2, cudaStreamNonBlocking);
        cudaEventCreateWithFlags(&evFork, cudaEventDisableTiming);
        cudaEventCreateWithFlags(&evJoin, cudaEventDisableTiming);
    }

    cudaFuncSetAttribute(mma_gemm<true, false>, cudaFuncAttributeMaxDynamicSharedMemorySize, SM_TOTAL);
    cudaFuncSetAttribute(mma_gemm_f16<true, true>, cudaFuncAttributeMaxDynamicSharedMemorySize, F_SM_TOTAL);
    cudaFuncSetAttribute(mma_gemm_wide, cudaFuncAttributeMaxDynamicSharedMemorySize, W_SM_TOTAL);

    const dim3 blk(512);
    const dim3 g_h((NNODES + 127) / 128, 1);
    const dim3 g_o((NNODES + 127) / 128, (NLAB + 255) / 256);
    const int agg_blocks = (NNODES * 32 + 255) / 256;

    // fork: CSR build chain on s2, input GEMM on main stream (independent)
    cudaEventRecord(evFork, 0);
    cudaStreamWaitEvent(s2, evFork, 0);

    hist_kernel<<<(E + 255) / 256, 256, 0, s2>>>(dst, E);
    scanA_kernel<<<NSCANB, 256, 0, s2>>>();
    scanB_kernel<<<1, 256, 0, s2>>>();
    scanC_kernel<<<NSCANB, 256, 0, s2>>>();
    scatter_kernel<<<(E + 255) / 256, 256, 0, s2>>>(src, dst, self_w, ppi_w, E);
    cudaEventRecord(evJoin, s2);

    // h = relu(x @ W_in + b_in)  (bf16 3-term: precision headroom, hides CSR)
    mma_gemm<true, false><<<g_h, blk, SM_TOTAL>>>(x, W_in, b_in, nullptr, ha, NNODES, DIN, DH);

    cudaStreamWaitEvent(0, evJoin, 0);

    // layer 1 (fp16 2-term)
    aggregate_kernel<<<agg_blocks, 256>>>(ha);
    mma_gemm_f16<true, true><<<g_h, blk, F_SM_TOTAL>>>(agg, W1, b1, res, hb, NNODES, DH, DH);
    // layer 2 (fp16 2-term)
    aggregate_kernel<<<agg_blocks, 256>>>(hb);
    mma_gemm_f16<true, true><<<g_h, blk, F_SM_TOTAL>>>(agg, W2, b2, res, ha, NNODES, DH, DH);
    // out = h @ W_out + b_out  (fp16 2-term wide kernel)
    mma_gemm_wide<<<g_o, blk, W_SM_TOTAL>>>(ha, W_out, b_out, out, NNODES, DH, NLAB);
}

// round 16
// speedup vs baseline: 1.2229x; 1.1045x over previous
#include <cuda_runtime.h>
#include <cuda_bf16.h>
#include <cuda_fp16.h>
#include <cstdint>

#define NNODES 50000
#define NEDGES 800000
#define DIN    256
#define DH     128
#define NLAB   1000
#define NSCANB 196   // ceil(50000/256)

// ---------------- scratch (static device allocations; no cudaMalloc) --------
__device__ float g_ha[NNODES * DH];
__device__ float g_hb[NNODES * DH];
__device__ float g_agg[NNODES * DH];
__device__ float g_res[NNODES * DH];
__device__ int   g_cnt[NNODES];          // zero-init; left zero after each call
__device__ int   g_rowptr[NNODES + 1];
__device__ int   g_cursor[NNODES];
__device__ int   g_bsum[NSCANB];
__device__ uint4 g_edge[NEDGES];         // {src, self_w, ppi_w, pad} AoS

// ---------------- helpers ----------------------------------------------------
__device__ __forceinline__ uint32_t smem_u32(const void* p) {
    uint32_t a;
    asm("{ .reg .u64 t; cvta.to.shared.u64 t, %1; cvt.u32.u64 %0, t; }" : "=r"(a) : "l"(p));
    return a;
}
__device__ __forceinline__ uint32_t pack_bf2(float e0, float e1) {
    // low half = bf16(e0), high half = bf16(e1)
    uint32_t r;
    asm("cvt.rn.satfinite.bf16x2.f32 %0, %1, %2;" : "=r"(r) : "f"(e1), "f"(e0));
    return r;
}
__device__ __forceinline__ uint32_t pack_h2(float e0, float e1) {
    __half2 h = __floats2half2_rn(e0, e1);   // e0 -> low
    return *reinterpret_cast<uint32_t*>(&h);
}
__device__ __forceinline__ float2 unpack_h2(uint32_t u) {
    __half2 h = *reinterpret_cast<__half2*>(&u);
    return __half22float2(h);
}

#define LDSM4(r, addr)                                                          \
    asm volatile("ldmatrix.sync.aligned.m8n8.x4.shared.b16 {%0,%1,%2,%3}, [%4];"\
        : "=r"((r)[0]), "=r"((r)[1]), "=r"((r)[2]), "=r"((r)[3]) : "r"(addr))
#define LDSM4T(r, addr)                                                         \
    asm volatile("ldmatrix.sync.aligned.m8n8.x4.trans.shared.b16 {%0,%1,%2,%3}, [%4];"\
        : "=r"((r)[0]), "=r"((r)[1]), "=r"((r)[2]), "=r"((r)[3]) : "r"(addr))
#define MMA16816(d, a, b)                                                       \
    asm volatile("mma.sync.aligned.m16n8k16.row.col.f32.bf16.bf16.f32 "         \
        "{%0,%1,%2,%3}, {%4,%5,%6,%7}, {%8,%9}, {%0,%1,%2,%3};"                 \
        : "+f"((d)[0]), "+f"((d)[1]), "+f"((d)[2]), "+f"((d)[3])                \
        : "r"((a)[0]), "r"((a)[1]), "r"((a)[2]), "r"((a)[3]),                   \
          "r"((b)[0]), "r"((b)[1]))
#define MMA16816H(d, a, b)                                                      \
    asm volatile("mma.sync.aligned.m16n8k16.row.col.f32.f16.f16.f32 "           \
        "{%0,%1,%2,%3}, {%4,%5,%6,%7}, {%8,%9}, {%0,%1,%2,%3};"                 \
        : "+f"((d)[0]), "+f"((d)[1]), "+f"((d)[2]), "+f"((d)[3])                \
        : "r"((a)[0]), "r"((a)[1]), "r"((a)[2]), "r"((a)[3]),                   \
          "r"((b)[0]), "r"((b)[1]))

// ---------------- CSR build -------------------------------------------------
__global__ void hist_kernel(const int* __restrict__ dst, int E) {
    int i = blockIdx.x * blockDim.x + threadIdx.x;
    if (i < E) atomicAdd(&g_cnt[dst[i]], 1);
}
__global__ void scanA_kernel() {
    __shared__ int wsum[8];
    int i = blockIdx.x * 256 + threadIdx.x;
    int lane = threadIdx.x & 31, wid = threadIdx.x >> 5;
    int v = (i < NNODES) ? g_cnt[i] : 0;
    #pragma unroll
    for (int off = 16; off > 0; off >>= 1) v += __shfl_down_sync(0xFFFFFFFFu, v, off);
    if (lane == 0) wsum[wid] = v;
    __syncthreads();
    if (threadIdx.x == 0) {
        int s = 0;
        #pragma unroll
        for (int w = 0; w < 8; w++) s += wsum[w];
        g_bsum[blockIdx.x] = s;
    }
}
__global__ void scanB_kernel() {
    __shared__ int wsc[8];
    int t = threadIdx.x;
    int lane = t & 31, wid = t >> 5;
    int v = (t < NSCANB) ? g_bsum[t] : 0;
    int incl = v;
    #pragma unroll
    for (int off = 1; off < 32; off <<= 1) {
        int u = __shfl_up_sync(0xFFFFFFFFu, incl, off);
        if (lane >= off) incl += u;
    }
    if (lane == 31) wsc[wid] = incl;
    __syncthreads();
    if (wid == 0) {
        int ws = (lane < 8) ? wsc[lane] : 0;
        #pragma unroll
        for (int off = 1; off < 8; off <<= 1) {
            int u = __shfl_up_sync(0xFFFFFFFFu, ws, off);
            if (lane >= off) ws += u;
        }
        if (lane < 8) wsc[lane] = ws;
    }
    __syncthreads();
    int excl = incl - v + (wid ? wsc[wid - 1] : 0);
    if (t < NSCANB) g_bsum[t] = excl;
    if (t == 255) g_rowptr[NNODES] = excl + v;
}
__global__ void scanC_kernel() {
    __shared__ int wsc[8];
    int i = blockIdx.x * 256 + threadIdx.x;
    int t = threadIdx.x, lane = t & 31, wid = t >> 5;
    int v = (i < NNODES) ? g_cnt[i] : 0;
    int incl = v;
    #pragma unroll
    for (int off = 1; off < 32; off <<= 1) {
        int u = __shfl_up_sync(0xFFFFFFFFu, incl, off);
        if (lane >= off) incl += u;
    }
    if (lane == 31) wsc[wid] = incl;
    __syncthreads();
    if (wid == 0) {
        int ws = (lane < 8) ? wsc[lane] : 0;
        #pragma unroll
        for (int off = 1; off < 8; off <<= 1) {
            int u = __shfl_up_sync(0xFFFFFFFFu, ws, off);
            if (lane >= off) ws += u;
        }
        if (lane < 8) wsc[lane] = ws;
    }
    __syncthreads();
    int excl = incl - v + (wid ? wsc[wid - 1] : 0) + g_bsum[blockIdx.x];
    if (i < NNODES) {
        g_rowptr[i] = excl;
        g_cursor[i] = excl;
        g_cnt[i] = 0;
    }
}
__global__ void scatter_kernel(const int* __restrict__ src, const int* __restrict__ dst,
                               const float* __restrict__ sw, const float* __restrict__ pw,
                               int E) {
    int i = blockIdx.x * blockDim.x + threadIdx.x;
    if (i < E) {
        int d = dst[i];
        int pos = atomicAdd(&g_cursor[d], 1);
        g_edge[pos] = make_uint4((uint32_t)src[i], __float_as_uint(sw[i]),
                                 __float_as_uint(pw[i]), 0u);
    }
}

// ---------------- aggregation: warp per dst node ----------------------------
__global__ void aggregate_kernel(const float* __restrict__ h) {
    int warp = (blockIdx.x * blockDim.x + threadIdx.x) >> 5;
    int lane = threadIdx.x & 31;
    if (warp >= NNODES) return;
    int beg = g_rowptr[warp];
    int end = g_rowptr[warp + 1];
    float4 as = make_float4(0.f, 0.f, 0.f, 0.f);
    float4 ap = make_float4(0.f, 0.f, 0.f, 0.f);
    int e = beg;
    for (; e + 1 < end; e += 2) {
        uint4 e0 = g_edge[e], e1 = g_edge[e + 1];
        int   s0 = (int)e0.x, s1 = (int)e1.x;
        float sw0 = __uint_as_float(e0.y), pw0 = __uint_as_float(e0.z);
        float sw1 = __uint_as_float(e1.y), pw1 = __uint_as_float(e1.z);
        float4 h0 = *reinterpret_cast<const float4*>(&h[(size_t)s0 * DH + lane * 4]);
        float4 h1 = *reinterpret_cast<const float4*>(&h[(size_t)s1 * DH + lane * 4]);
        as.x += sw0 * h0.x; as.y += sw0 * h0.y; as.z += sw0 * h0.z; as.w += sw0 * h0.w;
        ap.x += pw0 * h0.x; ap.y += pw0 * h0.y; ap.z += pw0 * h0.z; ap.w += pw0 * h0.w;
        as.x += sw1 * h1.x; as.y += sw1 * h1.y; as.z += sw1 * h1.z; as.w += sw1 * h1.w;
        ap.x += pw1 * h1.x; ap.y += pw1 * h1.y; ap.z += pw1 * h1.z; ap.w += pw1 * h1.w;
    }
    if (e < end) {
        uint4 e0 = g_edge[e];
        int   s0 = (int)e0.x;
        float sw0 = __uint_as_float(e0.y), pw0 = __uint_as_float(e0.z);
        float4 h0 = *reinterpret_cast<const float4*>(&h[(size_t)s0 * DH + lane * 4]);
        as.x += sw0 * h0.x; as.y += sw0 * h0.y; as.z += sw0 * h0.z; as.w += sw0 * h0.w;
        ap.x += pw0 * h0.x; ap.y += pw0 * h0.y; ap.z += pw0 * h0.z; ap.w += pw0 * h0.w;
    }
    *reinterpret_cast<float4*>(&g_res[(size_t)warp * DH + lane * 4]) = as;
    *reinterpret_cast<float4*>(&g_agg[(size_t)warp * DH + lane * 4]) = ap;
}

// ---------------- bf16-split GEMM on HMMA (128x128 block, 3-term) -----------
// Used only for the input GEMM (precision headroom; overlaps the CSR chain).
#define SA_STRIDE 80
#define SB_STRIDE 272
#define OFF_A_HI 0
#define OFF_A_LO 10240
#define OFF_B_HI 20480
#define OFF_B_LO 29184
#define BUF_SZ   37888
#define OFF_BIAS 75776
#define SM_TOTAL 76288

template<bool RELU, bool ADDRES>
__global__ __launch_bounds__(512)
void mma_gemm(const float* __restrict__ A, const float* __restrict__ B,
              const float* __restrict__ bias, const float* __restrict__ Res,
              float* __restrict__ C, int M, int K, int Nc) {
    extern __shared__ __align__(16) char smem[];
    const uint32_t sb = smem_u32(smem);
    const int tid  = threadIdx.x;
    const int wid  = tid >> 5;
    const int lane = tid & 31;
    const int rowBase = blockIdx.x * 128;
    const int colBase = blockIdx.y * 128;
    const int wm = (wid >> 2) * 32;
    const int wn = (wid & 3) * 32;
    float* bias_s = reinterpret_cast<float*>(smem + OFF_BIAS);

    if (tid < 128) {
        int gc = colBase + tid;
        bias_s[tid] = (gc < Nc) ? bias[gc] : 0.f;
    }

    float4 pa[2], pb[2];

    auto loadA = [&](int k0) {
        #pragma unroll
        for (int u = 0; u < 2; u++) {
            int it = tid + u * 512;
            int r  = it >> 3;
            int kq = (it & 7) << 2;
            int gr = rowBase + r;
            pa[u] = (gr < M) ? *reinterpret_cast<const float4*>(&A[(size_t)gr * K + k0 + kq])
                             : make_float4(0.f, 0.f, 0.f, 0.f);
        }
    };
    auto loadB = [&](int k0) {
        #pragma unroll
        for (int u = 0; u < 2; u++) {
            int it = tid + u * 512;
            int kr = it >> 5;
            int nq = (it & 31) << 2;
            int gc = colBase + nq;
            const float* Brow = &B[(size_t)(k0 + kr) * Nc];
            float4 v;
            if (gc + 3 < Nc) {
                v = *reinterpret_cast<const float4*>(&Brow[gc]);
            } else {
                v.x = (gc     < Nc) ? Brow[gc]     : 0.f;
                v.y = (gc + 1 < Nc) ? Brow[gc + 1] : 0.f;
                v.z = (gc + 2 < Nc) ? Brow[gc + 2] : 0.f;
                v.w = (gc + 3 < Nc) ? Brow[gc + 3] : 0.f;
            }
            pb[u] = v;
        }
    };
    auto storeAB = [&](int buf) {
        const int base = buf * BUF_SZ;
        #pragma unroll
        for (int u = 0; u < 2; u++) {
            int it = tid + u * 512;
            int r  = it >> 3;
            int kq = (it & 7) << 2;
            float4 v = pa[u];
            uint32_t hp01 = pack_bf2(v.x, v.y);
            uint32_t hp23 = pack_bf2(v.z, v.w);
            float hx = __uint_as_float(hp01 << 16);
            float hy = __uint_as_float(hp01 & 0xFFFF0000u);
            float hz = __uint_as_float(hp23 << 16);
            float hw = __uint_as_float(hp23 & 0xFFFF0000u);
            uint32_t lp01 = pack_bf2(v.x - hx, v.y - hy);
            uint32_t lp23 = pack_bf2(v.z - hz, v.w - hw);
            int ad = base + r * SA_STRIDE + kq * 2;
            *reinterpret_cast<uint2*>(smem + OFF_A_HI + ad) = make_uint2(hp01, hp23);
            *reinterpret_cast<uint2*>(smem + OFF_A_LO + ad) = make_uint2(lp01, lp23);
        }
        #pragma unroll
        for (int u = 0; u < 2; u++) {
            int it = tid + u * 512;
            int kr = it >> 5;
            int nq = (it & 31) << 2;
            float4 v = pb[u];
            uint32_t hp01 = pack_bf2(v.x, v.y);
            uint32_t hp23 = pack_bf2(v.z, v.w);
            float hx = __uint_as_float(hp01 << 16);
            float hy = __uint_as_float(hp01 & 0xFFFF0000u);
            float hz = __uint_as_float(hp23 << 16);
            float hw = __uint_as_float(hp23 & 0xFFFF0000u);
            uint32_t lp01 = pack_bf2(v.x - hx, v.y - hy);
            uint32_t lp23 = pack_bf2(v.z - hz, v.w - hw);
            int ad = base + kr * SB_STRIDE + nq * 2;
            *reinterpret_cast<uint2*>(smem + OFF_B_HI + ad) = make_uint2(hp01, hp23);
            *reinterpret_cast<uint2*>(smem + OFF_B_LO + ad) = make_uint2(lp01, lp23);
        }
    };

    float acc[2][4][4];
    #pragma unroll
    for (int mt = 0; mt < 2; mt++)
        #pragma unroll
        for (int nt = 0; nt < 4; nt++)
            #pragma unroll
            for (int q = 0; q < 4; q++) acc[mt][nt][q] = 0.f;

    const int nch = K >> 5;
    loadA(0); loadB(0);
    storeAB(0);
    if (nch > 1) { loadA(32); loadB(32); }
    __syncthreads();

    for (int ch = 0; ch < nch; ch++) {
        const int base = (ch & 1) * BUF_SZ;
        #pragma unroll
        for (int kk = 0; kk < 32; kk += 16) {
            uint32_t ahi[2][4], alo[2][4];
            #pragma unroll
            for (int mt = 0; mt < 2; mt++) {
                int row = wm + mt * 16 + (lane & 15);
                int col = kk + ((lane >> 4) << 3);
                uint32_t aadr = sb + OFF_A_HI + base + row * SA_STRIDE + col * 2;
                LDSM4(ahi[mt], aadr);
                LDSM4(alo[mt], aadr + (OFF_A_LO - OFF_A_HI));
            }
            #pragma unroll
            for (int g = 0; g < 2; g++) {
                int krow = kk + ((lane >> 3) & 1) * 8 + (lane & 7);
                int ncol = wn + g * 16 + ((lane >> 4) << 3);
                uint32_t badr = sb + OFF_B_HI + base + krow * SB_STRIDE + ncol * 2;
                uint32_t bh[4], bl[4];
                LDSM4T(bh, badr);
                LDSM4T(bl, badr + (OFF_B_LO - OFF_B_HI));
                #pragma unroll
                for (int half = 0; half < 2; half++) {
                    int nt = g * 2 + half;
                    #pragma unroll
                    for (int mt = 0; mt < 2; mt++) {
                        MMA16816(acc[mt][nt], ahi[mt], bh + 2 * half);
                        MMA16816(acc[mt][nt], ahi[mt], bl + 2 * half);
                        MMA16816(acc[mt][nt], alo[mt], bh + 2 * half);
                    }
                }
            }
        }
        if (ch + 1 < nch) {
            storeAB((ch + 1) & 1);
            if (ch + 2 < nch) { loadA((ch + 2) << 5); loadB((ch + 2) << 5); }
            __syncthreads();
        }
    }

    const int g4 = lane >> 2;
    const int t4 = lane & 3;
    #pragma unroll
    for (int mt = 0; mt < 2; mt++) {
        #pragma unroll
        for (int half = 0; half < 2; half++) {
            int gr = rowBase + wm + mt * 16 + g4 + half * 8;
            if (gr >= M) continue;
            #pragma unroll
            for (int nt = 0; nt < 4; nt++) {
                int cl = wn + nt * 8 + t4 * 2;
                int gc = colBase + cl;
                float v0 = acc[mt][nt][half * 2]     + bias_s[cl];
                float v1 = acc[mt][nt][half * 2 + 1] + bias_s[cl + 1];
                if (RELU) { v0 = fmaxf(v0, 0.f); v1 = fmaxf(v1, 0.f); }
                if (gc + 1 < Nc) {
                    if (ADDRES) {
                        float2 rr = *reinterpret_cast<const float2*>(&Res[(size_t)gr * Nc + gc]);
                        v0 += rr.x; v1 += rr.y;
                    }
                    *reinterpret_cast<float2*>(&C[(size_t)gr * Nc + gc]) = make_float2(v0, v1);
                } else if (gc < Nc) {
                    if (ADDRES) v0 += Res[(size_t)gr * Nc + gc];
                    C[(size_t)gr * Nc + gc] = v0;
                }
            }
        }
    }
}

// ---------------- fp16 2-term GEMM (128x128 block) for mid layers -----------
#define F_OFF_A_HI 0
#define F_OFF_A_LO 10240
#define F_OFF_B    20480
#define F_BUF_SZ   29184
#define F_OFF_BIAS 58368
#define F_SM_TOTAL 58880

template<bool RELU, bool ADDRES>
__global__ __launch_bounds__(512)
void mma_gemm_f16(const float* __restrict__ A, const float* __restrict__ B,
                  const float* __restrict__ bias, const float* __restrict__ Res,
                  float* __restrict__ C, int M, int K, int Nc) {
    extern __shared__ __align__(16) char smem[];
    const uint32_t sb = smem_u32(smem);
    const int tid  = threadIdx.x;
    const int wid  = tid >> 5;
    const int lane = tid & 31;
    const int rowBase = blockIdx.x * 128;
    const int colBase = blockIdx.y * 128;
    const int wm = (wid >> 2) * 32;
    const int wn = (wid & 3) * 32;
    float* bias_s = reinterpret_cast<float*>(smem + F_OFF_BIAS);

    if (tid < 128) {
        int gc = colBase + tid;
        bias_s[tid] = (gc < Nc) ? bias[gc] : 0.f;
    }

    float4 pa[2], pb[2];

    auto loadA = [&](int k0) {
        #pragma unroll
        for (int u = 0; u < 2; u++) {
            int it = tid + u * 512;
            int r  = it >> 3;
            int kq = (it & 7) << 2;
            int gr = rowBase + r;
            pa[u] = (gr < M) ? *reinterpret_cast<const float4*>(&A[(size_t)gr * K + k0 + kq])
                             : make_float4(0.f, 0.f, 0.f, 0.f);
        }
    };
    auto loadB = [&](int k0) {
        #pragma unroll
        for (int u = 0; u < 2; u++) {
            int it = tid + u * 512;
            int kr = it >> 5;
            int nq = (it & 31) << 2;
            int gc = colBase + nq;
            const float* Brow = &B[(size_t)(k0 + kr) * Nc];
            float4 v;
            if (gc + 3 < Nc) {
                v = *reinterpret_cast<const float4*>(&Brow[gc]);
            } else {
                v.x = (gc     < Nc) ? Brow[gc]     : 0.f;
                v.y = (gc + 1 < Nc) ? Brow[gc + 1] : 0.f;
                v.z = (gc + 2 < Nc) ? Brow[gc + 2] : 0.f;
                v.w = (gc + 3 < Nc) ? Brow[gc + 3] : 0.f;
            }
            pb[u] = v;
        }
    };
    auto storeAB = [&](int buf) {
        const int base = buf * F_BUF_SZ;
        #pragma unroll
        for (int u = 0; u < 2; u++) {
            int it = tid + u * 512;
            int r  = it >> 3;
            int kq = (it & 7) << 2;
            float4 v = pa[u];
            uint32_t hp01 = pack_h2(v.x, v.y);
            uint32_t hp23 = pack_h2(v.z, v.w);
            float2 h01 = unpack_h2(hp01);
            float2 h23 = unpack_h2(hp23);
            uint32_t lp01 = pack_h2(v.x - h01.x, v.y - h01.y);
            uint32_t lp23 = pack_h2(v.z - h23.x, v.w - h23.y);
            int ad = base + r * SA_STRIDE + kq * 2;
            *reinterpret_cast<uint2*>(smem + F_OFF_A_HI + ad) = make_uint2(hp01, hp23);
            *reinterpret_cast<uint2*>(smem + F_OFF_A_LO + ad) = make_uint2(lp01, lp23);
        }
        #pragma unroll
        for (int u = 0; u < 2; u++) {
            int it = tid + u * 512;
            int kr = it >> 5;
            int nq = (it & 31) << 2;
            float4 v = pb[u];
            uint32_t hp01 = pack_h2(v.x, v.y);
            uint32_t hp23 = pack_h2(v.z, v.w);
            int ad = base + kr * SB_STRIDE + nq * 2;
            *reinterpret_cast<uint2*>(smem + F_OFF_B + ad) = make_uint2(hp01, hp23);
        }
    };

    float acc[2][4][4];
    #pragma unroll
    for (int mt = 0; mt < 2; mt++)
        #pragma unroll
        for (int nt = 0; nt < 4; nt++)
            #pragma unroll
            for (int q = 0; q < 4; q++) acc[mt][nt][q] = 0.f;

    const int nch = K >> 5;
    loadA(0); loadB(0);
    storeAB(0);
    if (nch > 1) { loadA(32); loadB(32); }
    __syncthreads();

    for (int ch = 0; ch < nch; ch++) {
        const int base = (ch & 1) * F_BUF_SZ;
        #pragma unroll
        for (int kk = 0; kk < 32; kk += 16) {
            uint32_t ahi[2][4], alo[2][4];
            #pragma unroll
            for (int mt = 0; mt < 2; mt++) {
                int row = wm + mt * 16 + (lane & 15);
                int col = kk + ((lane >> 4) << 3);
                uint32_t aadr = sb + F_OFF_A_HI + base + row * SA_STRIDE + col * 2;
                LDSM4(ahi[mt], aadr);
                LDSM4(alo[mt], aadr + (F_OFF_A_LO - F_OFF_A_HI));
            }
            #pragma unroll
            for (int g = 0; g < 2; g++) {
                int krow = kk + ((lane >> 3) & 1) * 8 + (lane & 7);
                int ncol = wn + g * 16 + ((lane >> 4) << 3);
                uint32_t badr = sb + F_OFF_B + base + krow * SB_STRIDE + ncol * 2;
                uint32_t bh[4];
                LDSM4T(bh, badr);
                #pragma unroll
                for (int half = 0; half < 2; half++) {
                    int nt = g * 2 + half;
                    #pragma unroll
                    for (int mt = 0; mt < 2; mt++) {
                        MMA16816H(acc[mt][nt], ahi[mt], bh + 2 * half);
                        MMA16816H(acc[mt][nt], alo[mt], bh + 2 * half);
                    }
                }
            }
        }
        if (ch + 1 < nch) {
            storeAB((ch + 1) & 1);
            if (ch + 2 < nch) { loadA((ch + 2) << 5); loadB((ch + 2) << 5); }
            __syncthreads();
        }
    }

    const int g4 = lane >> 2;
    const int t4 = lane & 3;
    #pragma unroll
    for (int mt = 0; mt < 2; mt++) {
        #pragma unroll
        for (int half = 0; half < 2; half++) {
            int gr = rowBase + wm + mt * 16 + g4 + half * 8;
            if (gr >= M) continue;
            #pragma unroll
            for (int nt = 0; nt < 4; nt++) {
                int cl = wn + nt * 8 + t4 * 2;
                int gc = colBase + cl;
                float v0 = acc[mt][nt][half * 2]     + bias_s[cl];
                float v1 = acc[mt][nt][half * 2 + 1] + bias_s[cl + 1];
                if (RELU) { v0 = fmaxf(v0, 0.f); v1 = fmaxf(v1, 0.f); }
                if (gc + 1 < Nc) {
                    if (ADDRES) {
                        float2 rr = *reinterpret_cast<const float2*>(&Res[(size_t)gr * Nc + gc]);
                        v0 += rr.x; v1 += rr.y;
                    }
                    *reinterpret_cast<float2*>(&C[(size_t)gr * Nc + gc]) = make_float2(v0, v1);
                } else if (gc < Nc) {
                    if (ADDRES) v0 += Res[(size_t)gr * Nc + gc];
                    C[(size_t)gr * Nc + gc] = v0;
                }
            }
        }
    }
}

// ---------------- wide out GEMM: fp16 SINGLE-term, 128x256 block ------------
// C = fp16(A) @ fp16(B) + bias.  Both operands plain fp16 (err 2^-11 each);
// 1 MMA per k16 -- half the MMA work of the 2-term version on the biggest GEMM.
#define W_SA_STRIDE 80
#define W_SB_STRIDE 528
#define W_OFF_A    0
#define W_OFF_B    10240
#define W_BUF_SZ   27136
#define W_OFF_BIAS 54272
#define W_SM_TOTAL 55296

__global__ __launch_bounds__(512)
void mma_gemm_wide(const float* __restrict__ A, const float* __restrict__ B,
                   const float* __restrict__ bias, float* __restrict__ C,
                   int M, int K, int Nc) {
    extern __shared__ __align__(16) char smem[];
    const uint32_t sb = smem_u32(smem);
    const int tid  = threadIdx.x;
    const int wid  = tid >> 5;
    const int lane = tid & 31;
    const int rowBase = blockIdx.x * 128;
    const int colBase = blockIdx.y * 256;
    const int wm = (wid & 3) * 32;
    const int wn = (wid >> 2) * 64;
    float* bias_s = reinterpret_cast<float*>(smem + W_OFF_BIAS);

    if (tid < 256) {
        int gc = colBase + tid;
        bias_s[tid] = (gc < Nc) ? bias[gc] : 0.f;
    }

    float4 pa[2], pb[4];

    auto loadA = [&](int k0) {
        #pragma unroll
        for (int u = 0; u < 2; u++) {
            int it = tid + u * 512;
            int r  = it >> 3;
            int kq = (it & 7) << 2;
            int gr = rowBase + r;
            pa[u] = (gr < M) ? *reinterpret_cast<const float4*>(&A[(size_t)gr * K + k0 + kq])
                             : make_float4(0.f, 0.f, 0.f, 0.f);
        }
    };
    auto loadB = [&](int k0) {
        #pragma unroll
        for (int u = 0; u < 4; u++) {
            int it = tid + u * 512;
            int kr = it >> 6;
            int nq = (it & 63) << 2;
            int gc = colBase + nq;
            const float* Brow = &B[(size_t)(k0 + kr) * Nc];
            float4 v;
            if (gc + 3 < Nc) {
                v = *reinterpret_cast<const float4*>(&Brow[gc]);
            } else {
                v.x = (gc     < Nc) ? Brow[gc]     : 0.f;
                v.y = (gc + 1 < Nc) ? Brow[gc + 1] : 0.f;
                v.z = (gc + 2 < Nc) ? Brow[gc + 2] : 0.f;
                v.w = (gc + 3 < Nc) ? Brow[gc + 3] : 0.f;
            }
            pb[u] = v;
        }
    };
    auto storeAB = [&](int buf) {
        const int base = buf * W_BUF_SZ;
        #pragma unroll
        for (int u = 0; u < 2; u++) {
            int it = tid + u * 512;
            int r  = it >> 3;
            int kq = (it & 7) << 2;
            float4 v = pa[u];
            uint32_t hp01 = pack_h2(v.x, v.y);
            uint32_t hp23 = pack_h2(v.z, v.w);
            int ad = base + r * W_SA_STRIDE + kq * 2;
            *reinterpret_cast<uint2*>(smem + W_OFF_A + ad) = make_uint2(hp01, hp23);
        }
        #pragma unroll
        for (int u = 0; u < 4; u++) {
            int it = tid + u * 512;
            int kr = it >> 6;
            int nq = (it & 63) << 2;
            float4 v = pb[u];
            uint32_t hp01 = pack_h2(v.x, v.y);
            uint32_t hp23 = pack_h2(v.z, v.w);
            int ad = base + kr * W_SB_STRIDE + nq * 2;
            *reinterpret_cast<uint2*>(smem + W_OFF_B + ad) = make_uint2(hp01, hp23);
        }
    };

    float acc[2][8][4];
    #pragma unroll
    for (int mt = 0; mt < 2; mt++)
        #pragma unroll
        for (int nt = 0; nt < 8; nt++)
            #pragma unroll
            for (int q = 0; q < 4; q++) acc[mt][nt][q] = 0.f;

    const int nch = K >> 5;
    loadA(0); loadB(0);
    storeAB(0);
    if (nch > 1) { loadA(32); loadB(32); }
    __syncthreads();

    for (int ch = 0; ch < nch; ch++) {
        const int base = (ch & 1) * W_BUF_SZ;
        #pragma unroll
        for (int kk = 0; kk < 32; kk += 16) {
            uint32_t af[2][4];
            #pragma unroll
            for (int mt = 0; mt < 2; mt++) {
                int row = wm + mt * 16 + (lane & 15);
                int col = kk + ((lane >> 4) << 3);
                uint32_t aadr = sb + W_OFF_A + base + row * W_SA_STRIDE + col * 2;
                LDSM4(af[mt], aadr);
            }
            #pragma unroll
            for (int g = 0; g < 4; g++) {
                int krow = kk + ((lane >> 3) & 1) * 8 + (lane & 7);
                int ncol = wn + g * 16 + ((lane >> 4) << 3);
                uint32_t badr = sb + W_OFF_B + base + krow * W_SB_STRIDE + ncol * 2;
                uint32_t bh[4];
                LDSM4T(bh, badr);
                #pragma unroll
                for (int half = 0; half < 2; half++) {
                    int nt = g * 2 + half;
                    #pragma unroll
                    for (int mt = 0; mt < 2; mt++) {
                        MMA16816H(acc[mt][nt], af[mt], bh + 2 * half);
                    }
                }
            }
        }
        if (ch + 1 < nch) {
            storeAB((ch + 1) & 1);
            if (ch + 2 < nch) { loadA((ch + 2) << 5); loadB((ch + 2) << 5); }
            __syncthreads();
        }
    }

    const int g4 = lane >> 2;
    const int t4 = lane & 3;
    #pragma unroll
    for (int mt = 0; mt < 2; mt++) {
        #pragma unroll
        for (int half = 0; half < 2; half++) {
            int gr = rowBase + wm + mt * 16 + g4 + half * 8;
            if (gr >= M) continue;
            #pragma unroll
            for (int nt = 0; nt < 8; nt++) {
                int cl = wn + nt * 8 + t4 * 2;
                int gc = colBase + cl;
                float v0 = acc[mt][nt][half * 2]     + bias_s[cl];
                float v1 = acc[mt][nt][half * 2 + 1] + bias_s[cl + 1];
                if (gc + 1 < Nc) {
                    *reinterpret_cast<float2*>(&C[(size_t)gr * Nc + gc]) = make_float2(v0, v1);
                } else if (gc < Nc) {
                    C[(size_t)gr * Nc + gc] = v0;
                }
            }
        }
    }
}

// ---------------- launch ----------------------------------------------------
extern "C" void kernel_launch(void* const* d_in, const int* in_sizes, int n_in,
                              void* d_out, int out_size) {
    const float* x      = (const float*)d_in[0];
    const int*   src    = (const int*)  d_in[1];
    const int*   dst    = (const int*)  d_in[2];
    const float* self_w = (const float*)d_in[3];
    const float* ppi_w  = (const float*)d_in[4];
    const float* W_in   = (const float*)d_in[5];
    const float* b_in   = (const float*)d_in[6];
    const float* W1     = (const float*)d_in[7];
    const float* b1     = (const float*)d_in[8];
    const float* W2     = (const float*)d_in[9];
    const float* b2     = (const float*)d_in[10];
    const float* W_out  = (const float*)d_in[11];
    const float* b_out  = (const float*)d_in[12];
    float* out = (float*)d_out;
    const int E = in_sizes[1];

    float *ha, *hb, *agg, *res;
    cudaGetSymbolAddress((void**)&ha,  g_ha);
    cudaGetSymbolAddress((void**)&hb,  g_hb);
    cudaGetSymbolAddress((void**)&agg, g_agg);
    cudaGetSymbolAddress((void**)&res, g_res);

    static cudaStream_t s2 = nullptr;
    static cudaEvent_t evFork = nullptr, evJoin = nullptr;
    if (s2 == nullptr) {
        cudaStreamCreateWithFlags(&s2, cudaStreamNonBlocking);
        cudaEventCreateWithFlags(&evFork, cudaEventDisableTiming);
        cudaEventCreateWithFlags(&evJoin, cudaEventDisableTiming);
    }

    cudaFuncSetAttribute(mma_gemm<true, false>, cudaFuncAttributeMaxDynamicSharedMemorySize, SM_TOTAL);
    cudaFuncSetAttribute(mma_gemm_f16<true, true>, cudaFuncAttributeMaxDynamicSharedMemorySize, F_SM_TOTAL);
    cudaFuncSetAttribute(mma_gemm_wide, cudaFuncAttributeMaxDynamicSharedMemorySize, W_SM_TOTAL);

    const dim3 blk(512);
    const dim3 g_h((NNODES + 127) / 128, 1);
    const dim3 g_o((NNODES + 127) / 128, (NLAB + 255) / 256);
    const int agg_blocks = (NNODES * 32 + 255) / 256;

    // fork: CSR build chain on s2, input GEMM on main stream (independent)
    cudaEventRecord(evFork, 0);
    cudaStreamWaitEvent(s2, evFork, 0);

    hist_kernel<<<(E + 255) / 256, 256, 0, s2>>>(dst, E);
    scanA_kernel<<<NSCANB, 256, 0, s2>>>();
    scanB_kernel<<<1, 256, 0, s2>>>();
    scanC_kernel<<<NSCANB, 256, 0, s2>>>();
    scatter_kernel<<<(E + 255) / 256, 256, 0, s2>>>(src, dst, self_w, ppi_w, E);
    cudaEventRecord(evJoin, s2);

    // h = relu(x @ W_in + b_in)  (bf16 3-term: precision headroom, hides CSR)
    mma_gemm<true, false><<<g_h, blk, SM_TOTAL>>>(x, W_in, b_in, nullptr, ha, NNODES, DIN, DH);

    cudaStreamWaitEvent(0, evJoin, 0);

    // layer 1 (fp16 2-term)
    aggregate_kernel<<<agg_blocks, 256>>>(ha);
    mma_gemm_f16<true, true><<<g_h, blk, F_SM_TOTAL>>>(agg, W1, b1, res, hb, NNODES, DH, DH);
    // layer 2 (fp16 2-term)
    aggregate_kernel<<<agg_blocks, 256>>>(hb);
    mma_gemm_f16<true, true><<<g_h, blk, F_SM_TOTAL>>>(agg, W2, b2, res, ha, NNODES, DH, DH);
    // out = h @ W_out + b_out  (fp16 single-term wide kernel)
    mma_gemm_wide<<<g_o, blk, W_SM_TOTAL>>>(ha, W_out, b_out, out, NNODES, DH, NLAB);
}